// round 3
// baseline (speedup 1.0000x reference)
#include <cuda_runtime.h>
#include <math.h>

#define B_  2
#define T_  1024
#define D_  1024
#define H_  16
#define HD_ 64
#define FF_ 4096
#define L_  4
#define MREL 128
#define BT_ (B_*T_)   // 2048

// ---------------- scratch (no allocs allowed) ----------------
__device__ float g_h[BT_*D_];          // 8 MB
__device__ float g_hn[BT_*D_];         // 8 MB
__device__ float g_tmp[BT_*D_];        // 8 MB
__device__ float g_qkv[BT_*3*D_];      // 24 MB
__device__ float g_scores[(size_t)B_*H_*T_*T_]; // 128 MB
__device__ float g_attnout[BT_*D_];    // 8 MB
__device__ float g_ff1[BT_*2*FF_];     // 64 MB
__device__ float g_ffact[BT_*FF_];     // 32 MB

// ---------------- block reductions ----------------
__device__ __forceinline__ float block_reduce_sum(float v) {
    __shared__ float sh[33];
    int lane = threadIdx.x & 31, wid = threadIdx.x >> 5;
    #pragma unroll
    for (int o = 16; o > 0; o >>= 1) v += __shfl_xor_sync(0xffffffffu, v, o);
    if (lane == 0) sh[wid] = v;
    __syncthreads();
    if (wid == 0) {
        float t = (lane < 8) ? sh[lane] : 0.f;
        #pragma unroll
        for (int o = 4; o > 0; o >>= 1) t += __shfl_xor_sync(0xffffffffu, t, o);
        if (lane == 0) sh[32] = t;
    }
    __syncthreads();
    return sh[32];
}

__device__ __forceinline__ float block_reduce_max(float v) {
    __shared__ float sh[33];
    int lane = threadIdx.x & 31, wid = threadIdx.x >> 5;
    #pragma unroll
    for (int o = 16; o > 0; o >>= 1) v = fmaxf(v, __shfl_xor_sync(0xffffffffu, v, o));
    if (lane == 0) sh[wid] = v;
    __syncthreads();
    if (wid == 0) {
        float t = (lane < 8) ? sh[lane] : -1e30f;
        #pragma unroll
        for (int o = 4; o > 0; o >>= 1) t = fmaxf(t, __shfl_xor_sync(0xffffffffu, t, o));
        if (lane == 0) sh[32] = t;
    }
    __syncthreads();
    return sh[32];
}

// ---------------- generic GEMM: C = A(MxK) @ B(KxN) + bias[N] (+ Res) ----------------
template<bool HAS_RES>
__global__ void __launch_bounds__(256) gemm_kernel(
    const float* __restrict__ A, const float* __restrict__ Bm,
    const float* __restrict__ bias, const float* __restrict__ Res,
    float* __restrict__ C, int M, int N, int K)
{
    __shared__ float As[16][65];
    __shared__ float Bs[16][64];
    int tid = threadIdx.x;
    int tx = tid & 15, ty = tid >> 4;
    int m0 = blockIdx.y * 64, n0 = blockIdx.x * 64;

    float acc[4][4] = {};
    for (int k0 = 0; k0 < K; k0 += 16) {
        #pragma unroll
        for (int j = 0; j < 4; j++) {
            int i = tid + j * 256;
            int r = i >> 4, c = i & 15;
            As[c][r] = A[(size_t)(m0 + r) * K + k0 + c];
        }
        #pragma unroll
        for (int j = 0; j < 4; j++) {
            int i = tid + j * 256;
            int r = i >> 6, c = i & 63;
            Bs[r][c] = Bm[(size_t)(k0 + r) * N + n0 + c];
        }
        __syncthreads();
        #pragma unroll
        for (int k = 0; k < 16; k++) {
            float a[4], bb[4];
            #pragma unroll
            for (int i = 0; i < 4; i++) a[i] = As[k][ty * 4 + i];
            #pragma unroll
            for (int j = 0; j < 4; j++) bb[j] = Bs[k][tx * 4 + j];
            #pragma unroll
            for (int i = 0; i < 4; i++)
                #pragma unroll
                for (int j = 0; j < 4; j++)
                    acc[i][j] += a[i] * bb[j];
        }
        __syncthreads();
    }
    #pragma unroll
    for (int i = 0; i < 4; i++) {
        int m = m0 + ty * 4 + i;
        #pragma unroll
        for (int j = 0; j < 4; j++) {
            int n = n0 + tx * 4 + j;
            float v = acc[i][j] + bias[n];
            if (HAS_RES) v += Res[(size_t)m * N + n];
            C[(size_t)m * N + n] = v;
        }
    }
}

// ---------------- LayerNorm over rows of D ----------------
__global__ void __launch_bounds__(256) ln_kernel(
    const float* __restrict__ x, const float* __restrict__ g,
    const float* __restrict__ b, float* __restrict__ y)
{
    int row = blockIdx.x;
    const float* xr = x + (size_t)row * D_;
    float v[4];
    float s = 0.f;
    #pragma unroll
    for (int j = 0; j < 4; j++) { v[j] = xr[threadIdx.x + j * 256]; s += v[j]; }
    float mean = block_reduce_sum(s) * (1.0f / D_);
    float var = 0.f;
    #pragma unroll
    for (int j = 0; j < 4; j++) { float d0 = v[j] - mean; var += d0 * d0; }
    var = block_reduce_sum(var) * (1.0f / D_);
    float rstd = rsqrtf(var + 1e-5f);
    float* yr = y + (size_t)row * D_;
    #pragma unroll
    for (int j = 0; j < 4; j++) {
        int c = threadIdx.x + j * 256;
        yr[c] = (v[j] - mean) * rstd * g[c] + b[c];
    }
}

// ---------------- RoPE (in-place on q and k parts of qkv) ----------------
__global__ void __launch_bounds__(256) rope_kernel(float* __restrict__ qkv)
{
    int idx = blockIdx.x * 256 + threadIdx.x;  // B*T*H*32
    int p = idx & 31;
    int h = (idx >> 5) & 15;
    int t = (idx >> 9) & 1023;
    int b = idx >> 19;
    int ifx = (2 * p) & 31;   // emb[t, j] = t * inv_freq[j mod 32], j = 2p
    float theta = (float)t * powf(10000.0f, -(float)(2 * ifx) * (1.0f / 64.0f));
    float s, c;
    sincosf(theta, &s, &c);
    size_t baseq = ((size_t)(b * T_ + t) * 3 + 0) * D_ + h * 64 + 2 * p;
    size_t basek = baseq + D_;
    float x1 = qkv[baseq], x2 = qkv[baseq + 1];
    qkv[baseq]     = x1 * c - x2 * s;
    qkv[baseq + 1] = x1 * s + x2 * c;
    x1 = qkv[basek]; x2 = qkv[basek + 1];
    qkv[basek]     = x1 * c - x2 * s;
    qkv[basek + 1] = x1 * s + x2 * c;
}

// ---------------- scores = Q K^T * scale + rel_bias ----------------
__global__ void __launch_bounds__(256) score_kernel(
    const float* __restrict__ qkv, const float* __restrict__ relb,
    float* __restrict__ scores)
{
    __shared__ float Qs[64][65];
    __shared__ float Ks[64][65];
    int bh = blockIdx.z, b = bh >> 4, h = bh & 15;
    int q0 = blockIdx.y * 64, k0 = blockIdx.x * 64;
    int tid = threadIdx.x, tx = tid & 15, ty = tid >> 4;

    #pragma unroll
    for (int j = 0; j < 16; j++) {
        int i = tid + j * 256;
        int r = i >> 6, d = i & 63;
        Qs[d][r] = qkv[((size_t)(b * T_ + q0 + r) * 3 + 0) * D_ + h * 64 + d];
        Ks[d][r] = qkv[((size_t)(b * T_ + k0 + r) * 3 + 1) * D_ + h * 64 + d];
    }
    __syncthreads();

    float acc[4][4] = {};
    #pragma unroll 8
    for (int d = 0; d < 64; d++) {
        float a[4], bb[4];
        #pragma unroll
        for (int i = 0; i < 4; i++) a[i] = Qs[d][ty * 4 + i];
        #pragma unroll
        for (int j = 0; j < 4; j++) bb[j] = Ks[d][tx * 4 + j];
        #pragma unroll
        for (int i = 0; i < 4; i++)
            #pragma unroll
            for (int j = 0; j < 4; j++)
                acc[i][j] += a[i] * bb[j];
    }

    #pragma unroll
    for (int i = 0; i < 4; i++) {
        int qi = q0 + ty * 4 + i;
        #pragma unroll
        for (int j = 0; j < 4; j++) {
            int kj = k0 + tx * 4 + j;
            int r = kj - qi;
            r = min(max(r, -MREL), MREL) + MREL;
            scores[((size_t)bh * T_ + qi) * T_ + kj] = acc[i][j] * 0.125f + relb[r * H_ + h];
        }
    }
}

// ---------------- softmax over rows of length T ----------------
__global__ void __launch_bounds__(256) softmax_kernel(float* __restrict__ scores)
{
    size_t row = blockIdx.x;
    float* r = scores + row * (size_t)T_;
    float v[4];
    float mx = -1e30f;
    #pragma unroll
    for (int j = 0; j < 4; j++) { v[j] = r[threadIdx.x + j * 256]; mx = fmaxf(mx, v[j]); }
    mx = block_reduce_max(mx);
    float s = 0.f;
    #pragma unroll
    for (int j = 0; j < 4; j++) { v[j] = __expf(v[j] - mx); s += v[j]; }
    s = block_reduce_sum(s);
    float inv = 1.0f / s;
    #pragma unroll
    for (int j = 0; j < 4; j++) r[threadIdx.x + j * 256] = v[j] * inv;
}

// ---------------- out = attn @ V  (writes (B,T,H*HD) layout) ----------------
__global__ void __launch_bounds__(256) av_kernel(
    const float* __restrict__ scores, const float* __restrict__ qkv,
    float* __restrict__ out)
{
    __shared__ float Ss[64][65];
    __shared__ float Vs[64][65];
    int bh = blockIdx.y, b = bh >> 4, h = bh & 15;
    int q0 = blockIdx.x * 64;
    int tid = threadIdx.x, tx = tid & 15, ty = tid >> 4;

    float acc[4][4] = {};
    for (int kt = 0; kt < T_; kt += 64) {
        #pragma unroll
        for (int j = 0; j < 16; j++) {
            int i = tid + j * 256;
            int r = i >> 6, c = i & 63;
            Ss[c][r] = scores[((size_t)bh * T_ + q0 + r) * T_ + kt + c];
            Vs[r][c] = qkv[((size_t)(b * T_ + kt + r) * 3 + 2) * D_ + h * 64 + c];
        }
        __syncthreads();
        #pragma unroll 8
        for (int k = 0; k < 64; k++) {
            float a[4], bb[4];
            #pragma unroll
            for (int i = 0; i < 4; i++) a[i] = Ss[k][ty * 4 + i];
            #pragma unroll
            for (int j = 0; j < 4; j++) bb[j] = Vs[k][tx * 4 + j];
            #pragma unroll
            for (int i = 0; i < 4; i++)
                #pragma unroll
                for (int j = 0; j < 4; j++)
                    acc[i][j] += a[i] * bb[j];
        }
        __syncthreads();
    }
    #pragma unroll
    for (int i = 0; i < 4; i++) {
        int q = q0 + ty * 4 + i;
        #pragma unroll
        for (int j = 0; j < 4; j++) {
            out[(size_t)(b * T_ + q) * D_ + h * 64 + tx * 4 + j] = acc[i][j];
        }
    }
}

// ---------------- GeGLU: ffact = a * gelu_exact(gate) ----------------
__global__ void __launch_bounds__(256) geglu_kernel(
    const float* __restrict__ ff1, float* __restrict__ ffact)
{
    int idx = blockIdx.x * 256 + threadIdx.x;   // BT * FF
    int m = idx >> 12;          // FF = 4096
    int f = idx & 4095;
    float a = ff1[(size_t)m * (2 * FF_) + f];
    float g = ff1[(size_t)m * (2 * FF_) + FF_ + f];
    float ge = 0.5f * g * (1.0f + erff(g * 0.70710678118654752f));
    ffact[idx] = a * ge;
}

// ---------------- final scaling epilogue ----------------
__global__ void __launch_bounds__(256) final_kernel(
    const float* __restrict__ o, const float* __restrict__ alpha,
    const float* __restrict__ beta, const float* __restrict__ alpha_scale,
    const float* __restrict__ beta_scale, float* __restrict__ out)
{
    int row = blockIdx.x;
    const float* orow = o + (size_t)row * D_;
    float v[4];
    float ss = 0.f;
    #pragma unroll
    for (int j = 0; j < 4; j++) { v[j] = orow[threadIdx.x + j * 256]; ss += v[j] * v[j]; }
    ss = block_reduce_sum(ss);
    float ms = sqrtf(ss);
    float a_s = fminf(fmaxf(alpha_scale[0], 0.f), 1.f);
    float sc = 1.0f + alpha[0] * a_s * fminf(ms, 5.0f);
    float bb = beta[0] * beta_scale[0];
    #pragma unroll
    for (int j = 0; j < 4; j++) {
        int c = threadIdx.x + j * 256;
        float val = v[j] * sc + bb;
        val = fminf(fmaxf(val, -10.0f), 10.0f);
        out[(size_t)row * D_ + c] = val + v[j];
    }
}

// ---------------- launch ----------------
extern "C" void kernel_launch(void* const* d_in, const int* in_sizes, int n_in,
                              void* d_out, int out_size)
{
    const float* x           = (const float*)d_in[0];
    const float* context     = (const float*)d_in[1];
    const float* W_in        = (const float*)d_in[2];
    const float* b_in        = (const float*)d_in[3];
    const float* ln_in_g     = (const float*)d_in[4];
    const float* ln_in_b     = (const float*)d_in[5];
    const float* ln1_g       = (const float*)d_in[6];
    const float* ln1_b       = (const float*)d_in[7];
    const float* Wqkv        = (const float*)d_in[8];
    const float* bqkv        = (const float*)d_in[9];
    const float* Wproj       = (const float*)d_in[10];
    const float* bproj       = (const float*)d_in[11];
    const float* rel_bias    = (const float*)d_in[12];
    const float* ln2_g       = (const float*)d_in[13];
    const float* ln2_b       = (const float*)d_in[14];
    const float* Wfc1        = (const float*)d_in[15];
    const float* bfc1        = (const float*)d_in[16];
    const float* Wfc2        = (const float*)d_in[17];
    const float* bfc2        = (const float*)d_in[18];
    const float* ln_f_g      = (const float*)d_in[19];
    const float* ln_f_b      = (const float*)d_in[20];
    const float* W_out       = (const float*)d_in[21];
    const float* b_out       = (const float*)d_in[22];
    const float* alpha       = (const float*)d_in[23];
    const float* beta        = (const float*)d_in[24];
    const float* alpha_scale = (const float*)d_in[25];
    const float* beta_scale  = (const float*)d_in[26];
    float* out = (float*)d_out;

    float *h, *hn, *tmp, *qkv, *scores, *attnout, *ff1, *ffact;
    cudaGetSymbolAddress((void**)&h,       g_h);
    cudaGetSymbolAddress((void**)&hn,      g_hn);
    cudaGetSymbolAddress((void**)&tmp,     g_tmp);
    cudaGetSymbolAddress((void**)&qkv,     g_qkv);
    cudaGetSymbolAddress((void**)&scores,  g_scores);
    cudaGetSymbolAddress((void**)&attnout, g_attnout);
    cudaGetSymbolAddress((void**)&ff1,     g_ff1);
    cudaGetSymbolAddress((void**)&ffact,   g_ffact);

    // pre: h = LN(x @ W_in + b_in + context)
    gemm_kernel<true><<<dim3(D_/64, BT_/64), 256>>>(x, W_in, b_in, context, tmp, BT_, D_, D_);
    ln_kernel<<<BT_, 256>>>(tmp, ln_in_g, ln_in_b, h);

    for (int l = 0; l < L_; l++) {
        // attention block
        ln_kernel<<<BT_, 256>>>(h, ln1_g + l*D_, ln1_b + l*D_, hn);
        gemm_kernel<false><<<dim3(3*D_/64, BT_/64), 256>>>(
            hn, Wqkv + (size_t)l*D_*3*D_, bqkv + l*3*D_, nullptr, qkv, BT_, 3*D_, D_);
        rope_kernel<<<(B_*T_*H_*32)/256, 256>>>(qkv);
        score_kernel<<<dim3(T_/64, T_/64, B_*H_), 256>>>(
            qkv, rel_bias + (size_t)l*(2*MREL+1)*H_, scores);
        softmax_kernel<<<B_*H_*T_, 256>>>(scores);
        av_kernel<<<dim3(T_/64, B_*H_), 256>>>(scores, qkv, attnout);
        gemm_kernel<true><<<dim3(D_/64, BT_/64), 256>>>(
            attnout, Wproj + (size_t)l*D_*D_, bproj + l*D_, h, h, BT_, D_, D_);

        // FFN block (GeGLU)
        ln_kernel<<<BT_, 256>>>(h, ln2_g + l*D_, ln2_b + l*D_, hn);
        gemm_kernel<false><<<dim3(2*FF_/64, BT_/64), 256>>>(
            hn, Wfc1 + (size_t)l*D_*2*FF_, bfc1 + l*2*FF_, nullptr, ff1, BT_, 2*FF_, D_);
        geglu_kernel<<<(BT_*FF_)/256, 256>>>(ff1, ffact);
        gemm_kernel<true><<<dim3(D_/64, BT_/64), 256>>>(
            ffact, Wfc2 + (size_t)l*FF_*D_, bfc2 + l*D_, h, h, BT_, D_, FF_);
    }

    // post: o = LN(h) @ W_out + b_out, then the norm/clip epilogue
    ln_kernel<<<BT_, 256>>>(h, ln_f_g, ln_f_b, hn);
    gemm_kernel<false><<<dim3(D_/64, BT_/64), 256>>>(hn, W_out, b_out, nullptr, tmp, BT_, D_, D_);
    final_kernel<<<BT_, 256>>>(tmp, alpha, beta, alpha_scale, beta_scale, out);
}

// round 6
// speedup vs baseline: 1.3666x; 1.3666x over previous
#include <cuda_runtime.h>
#include <math.h>
#include <stdint.h>

#define B_  2
#define T_  1024
#define D_  1024
#define H_  16
#define HD_ 64
#define FF_ 4096
#define L_  4
#define MREL 128
#define BT_ (B_*T_)   // 2048

// ---------------- scratch (no allocs allowed) ----------------
__device__ float g_h[BT_*D_];          // 8 MB
__device__ float g_hn[BT_*D_];         // 8 MB
__device__ float g_tmp[BT_*D_];        // 8 MB
__device__ float g_qkv[BT_*3*D_];      // 24 MB
__device__ float g_scores[(size_t)B_*H_*T_*T_]; // 128 MB
__device__ float g_attnout[BT_*D_];    // 8 MB
__device__ float g_ff1[BT_*2*FF_];     // 64 MB
__device__ float g_ffact[BT_*FF_];     // 32 MB

// ================= 3xTF32 mma.sync GEMM =================
// C[M,N] = A[M,K] @ W[K,N] + bias[N] (+ Res)
// Each operand split: x = hi + lo (hi = tf32(x), lo = tf32(x - hi)).
// D += hi*hi + hi*lo + lo*hi  -> ~fp32 precision on tensor pipe.
// CTA tile 128x128x32, 256 threads (8 warps, 2x4), warp tile 64x32.
#define BM 128
#define BN 128
#define BK 32
#define SSTRIDE 132
#define STAGE_F (BK*SSTRIDE)             // 4224 floats
#define G_SMEM_BYTES (8*STAGE_F*4)       // hi/lo x A/B x 2 stages = 135168 B

__device__ __forceinline__ float to_tf32(float x) {
    float r; asm("cvt.rna.tf32.f32 %0, %1;" : "=f"(r) : "f"(x)); return r;
}

__device__ __forceinline__ void mma_tf32(float c[4], const uint32_t a[4], const uint32_t b[2]) {
    asm volatile(
        "mma.sync.aligned.m16n8k8.row.col.f32.tf32.tf32.f32 "
        "{%0,%1,%2,%3}, {%4,%5,%6,%7}, {%8,%9}, {%0,%1,%2,%3};"
        : "+f"(c[0]), "+f"(c[1]), "+f"(c[2]), "+f"(c[3])
        : "r"(a[0]), "r"(a[1]), "r"(a[2]), "r"(a[3]), "r"(b[0]), "r"(b[1]));
}

template<bool HAS_RES>
__global__ void __launch_bounds__(256) gemm_mma(
    const float* __restrict__ A, const float* __restrict__ W,
    const float* __restrict__ bias, const float* __restrict__ Res,
    float* __restrict__ C, int M, int N, int K)
{
    extern __shared__ float sm[];
    float* AsHi = sm;                    // [2][32][132]
    float* AsLo = sm + 2*STAGE_F;
    float* BsHi = sm + 4*STAGE_F;
    float* BsLo = sm + 6*STAGE_F;

    const int tid = threadIdx.x;
    const int lane = tid & 31, wid = tid >> 5;
    const int wm = wid >> 2, wn = wid & 3;      // 2 x 4 warp grid
    const int m0 = blockIdx.y * BM, n0 = blockIdx.x * BN;
    const int ra = lane >> 2, ca = lane & 3;

    float acc[4][4][4];
    #pragma unroll
    for (int i = 0; i < 4; i++)
        #pragma unroll
        for (int j = 0; j < 4; j++)
            #pragma unroll
            for (int r = 0; r < 4; r++) acc[i][j][r] = 0.f;

    const int ar = tid >> 3, aj = tid & 7;      // A: row ar+32i, k-slot aj
    const int bkr = tid >> 5, bjn = tid & 31;   // B: k-row bkr+8i, n-group bjn

    float4 va[4], vb[4];

    auto load_g = [&](int kc) {
        #pragma unroll
        for (int i = 0; i < 4; i++) {
            int r = ar + i * 32;
            va[i] = *(const float4*)(A + (size_t)(m0 + r) * K + kc + 4 * aj);
        }
        #pragma unroll
        for (int i = 0; i < 4; i++) {
            int kr = bkr + i * 8;
            vb[i] = *(const float4*)(W + (size_t)(kc + kr) * N + n0 + 4 * bjn);
        }
    };
    auto store_s = [&](int s) {
        float* ah = AsHi + s * STAGE_F;
        float* al = AsLo + s * STAGE_F;
        float* bh = BsHi + s * STAGE_F;
        float* bl = BsLo + s * STAGE_F;
        #pragma unroll
        for (int i = 0; i < 4; i++) {
            int r = ar + i * 32;
            float hx = to_tf32(va[i].x), hy = to_tf32(va[i].y);
            float hz = to_tf32(va[i].z), hw = to_tf32(va[i].w);
            ah[(4 * aj + 0) * SSTRIDE + r] = hx;
            ah[(4 * aj + 1) * SSTRIDE + r] = hy;
            ah[(4 * aj + 2) * SSTRIDE + r] = hz;
            ah[(4 * aj + 3) * SSTRIDE + r] = hw;
            al[(4 * aj + 0) * SSTRIDE + r] = to_tf32(va[i].x - hx);
            al[(4 * aj + 1) * SSTRIDE + r] = to_tf32(va[i].y - hy);
            al[(4 * aj + 2) * SSTRIDE + r] = to_tf32(va[i].z - hz);
            al[(4 * aj + 3) * SSTRIDE + r] = to_tf32(va[i].w - hw);
        }
        #pragma unroll
        for (int i = 0; i < 4; i++) {
            int kr = bkr + i * 8;
            float4 hv, lv;
            hv.x = to_tf32(vb[i].x); lv.x = to_tf32(vb[i].x - hv.x);
            hv.y = to_tf32(vb[i].y); lv.y = to_tf32(vb[i].y - hv.y);
            hv.z = to_tf32(vb[i].z); lv.z = to_tf32(vb[i].z - hv.z);
            hv.w = to_tf32(vb[i].w); lv.w = to_tf32(vb[i].w - hv.w);
            *(float4*)(bh + kr * SSTRIDE + 4 * bjn) = hv;
            *(float4*)(bl + kr * SSTRIDE + 4 * bjn) = lv;
        }
    };
    auto compute = [&](int s) {
        const float* ah = AsHi + s * STAGE_F;
        const float* al = AsLo + s * STAGE_F;
        const float* bh = BsHi + s * STAGE_F;
        const float* bl = BsLo + s * STAGE_F;
        #pragma unroll
        for (int ks = 0; ks < 4; ks++) {
            const int c = ks * 8 + ca;
            uint32_t afh[4][4], afl[4][4], bfh[4][2], bfl[4][2];
            #pragma unroll
            for (int mt = 0; mt < 4; mt++) {
                int r = wm * 64 + mt * 16 + ra;
                afh[mt][0] = __float_as_uint(ah[c * SSTRIDE + r]);
                afh[mt][1] = __float_as_uint(ah[c * SSTRIDE + r + 8]);
                afh[mt][2] = __float_as_uint(ah[(c + 4) * SSTRIDE + r]);
                afh[mt][3] = __float_as_uint(ah[(c + 4) * SSTRIDE + r + 8]);
                afl[mt][0] = __float_as_uint(al[c * SSTRIDE + r]);
                afl[mt][1] = __float_as_uint(al[c * SSTRIDE + r + 8]);
                afl[mt][2] = __float_as_uint(al[(c + 4) * SSTRIDE + r]);
                afl[mt][3] = __float_as_uint(al[(c + 4) * SSTRIDE + r + 8]);
            }
            #pragma unroll
            for (int nt = 0; nt < 4; nt++) {
                int n = wn * 32 + nt * 8 + ra;
                bfh[nt][0] = __float_as_uint(bh[c * SSTRIDE + n]);
                bfh[nt][1] = __float_as_uint(bh[(c + 4) * SSTRIDE + n]);
                bfl[nt][0] = __float_as_uint(bl[c * SSTRIDE + n]);
                bfl[nt][1] = __float_as_uint(bl[(c + 4) * SSTRIDE + n]);
            }
            #pragma unroll
            for (int mt = 0; mt < 4; mt++)
                #pragma unroll
                for (int nt = 0; nt < 4; nt++) {
                    mma_tf32(acc[mt][nt], afh[mt], bfl[nt]);   // hi*lo
                    mma_tf32(acc[mt][nt], afl[mt], bfh[nt]);   // lo*hi
                    mma_tf32(acc[mt][nt], afh[mt], bfh[nt]);   // hi*hi
                }
        }
    };

    // prologue
    load_g(0);
    store_s(0);
    __syncthreads();

    const int NC = K / BK;
    for (int c0 = 0; c0 < NC; c0++) {
        const int s = c0 & 1;
        if (c0 + 1 < NC) load_g((c0 + 1) * BK);
        compute(s);
        if (c0 + 1 < NC) store_s(s ^ 1);
        __syncthreads();
    }

    // epilogue: fragment (mt,nt): rows m, m+8; cols n + {0,1} via float2
    const int cb = (lane & 3) * 2;
    #pragma unroll
    for (int mt = 0; mt < 4; mt++) {
        #pragma unroll
        for (int nt = 0; nt < 4; nt++) {
            int m = m0 + wm * 64 + mt * 16 + ra;
            int n = n0 + wn * 32 + nt * 8 + cb;
            float2 bv = *(const float2*)(bias + n);
            float2 v0, v1;
            v0.x = acc[mt][nt][0] + bv.x; v0.y = acc[mt][nt][1] + bv.y;
            v1.x = acc[mt][nt][2] + bv.x; v1.y = acc[mt][nt][3] + bv.y;
            if (HAS_RES) {
                float2 r0 = *(const float2*)(Res + (size_t)m * N + n);
                float2 r1 = *(const float2*)(Res + (size_t)(m + 8) * N + n);
                v0.x += r0.x; v0.y += r0.y; v1.x += r1.x; v1.y += r1.y;
            }
            *(float2*)(C + (size_t)m * N + n) = v0;
            *(float2*)(C + (size_t)(m + 8) * N + n) = v1;
        }
    }
}

// ---------------- block reductions ----------------
__device__ __forceinline__ float block_reduce_sum(float v) {
    __shared__ float sh[33];
    int lane = threadIdx.x & 31, wid = threadIdx.x >> 5;
    #pragma unroll
    for (int o = 16; o > 0; o >>= 1) v += __shfl_xor_sync(0xffffffffu, v, o);
    if (lane == 0) sh[wid] = v;
    __syncthreads();
    if (wid == 0) {
        float t = (lane < 8) ? sh[lane] : 0.f;
        #pragma unroll
        for (int o = 4; o > 0; o >>= 1) t += __shfl_xor_sync(0xffffffffu, t, o);
        if (lane == 0) sh[32] = t;
    }
    __syncthreads();
    return sh[32];
}

__device__ __forceinline__ float block_reduce_max(float v) {
    __shared__ float sh[33];
    int lane = threadIdx.x & 31, wid = threadIdx.x >> 5;
    #pragma unroll
    for (int o = 16; o > 0; o >>= 1) v = fmaxf(v, __shfl_xor_sync(0xffffffffu, v, o));
    if (lane == 0) sh[wid] = v;
    __syncthreads();
    if (wid == 0) {
        float t = (lane < 8) ? sh[lane] : -1e30f;
        #pragma unroll
        for (int o = 4; o > 0; o >>= 1) t = fmaxf(t, __shfl_xor_sync(0xffffffffu, t, o));
        if (lane == 0) sh[32] = t;
    }
    __syncthreads();
    return sh[32];
}

// ---------------- LayerNorm over rows of D ----------------
__global__ void __launch_bounds__(256) ln_kernel(
    const float* __restrict__ x, const float* __restrict__ g,
    const float* __restrict__ b, float* __restrict__ y)
{
    int row = blockIdx.x;
    const float* xr = x + (size_t)row * D_;
    float v[4];
    float s = 0.f;
    #pragma unroll
    for (int j = 0; j < 4; j++) { v[j] = xr[threadIdx.x + j * 256]; s += v[j]; }
    float mean = block_reduce_sum(s) * (1.0f / D_);
    float var = 0.f;
    #pragma unroll
    for (int j = 0; j < 4; j++) { float d0 = v[j] - mean; var += d0 * d0; }
    var = block_reduce_sum(var) * (1.0f / D_);
    float rstd = rsqrtf(var + 1e-5f);
    float* yr = y + (size_t)row * D_;
    #pragma unroll
    for (int j = 0; j < 4; j++) {
        int c = threadIdx.x + j * 256;
        yr[c] = (v[j] - mean) * rstd * g[c] + b[c];
    }
}

// ---------------- RoPE (in-place on q and k parts of qkv) ----------------
__global__ void __launch_bounds__(256) rope_kernel(float* __restrict__ qkv)
{
    int idx = blockIdx.x * 256 + threadIdx.x;  // B*T*H*32
    int p = idx & 31;
    int h = (idx >> 5) & 15;
    int t = (idx >> 9) & 1023;
    int b = idx >> 19;
    int ifx = (2 * p) & 31;
    float theta = (float)t * powf(10000.0f, -(float)(2 * ifx) * (1.0f / 64.0f));
    float s, c;
    sincosf(theta, &s, &c);
    size_t baseq = ((size_t)(b * T_ + t) * 3 + 0) * D_ + h * 64 + 2 * p;
    size_t basek = baseq + D_;
    float x1 = qkv[baseq], x2 = qkv[baseq + 1];
    qkv[baseq]     = x1 * c - x2 * s;
    qkv[baseq + 1] = x1 * s + x2 * c;
    x1 = qkv[basek]; x2 = qkv[basek + 1];
    qkv[basek]     = x1 * c - x2 * s;
    qkv[basek + 1] = x1 * s + x2 * c;
}

// ---------------- scores = Q K^T * scale + rel_bias ----------------
__global__ void __launch_bounds__(256) score_kernel(
    const float* __restrict__ qkv, const float* __restrict__ relb,
    float* __restrict__ scores)
{
    __shared__ float Qs[64][65];
    __shared__ float Ks[64][65];
    int bh = blockIdx.z, b = bh >> 4, h = bh & 15;
    int q0 = blockIdx.y * 64, k0 = blockIdx.x * 64;
    int tid = threadIdx.x, tx = tid & 15, ty = tid >> 4;

    #pragma unroll
    for (int j = 0; j < 16; j++) {
        int i = tid + j * 256;
        int r = i >> 6, d = i & 63;
        Qs[d][r] = qkv[((size_t)(b * T_ + q0 + r) * 3 + 0) * D_ + h * 64 + d];
        Ks[d][r] = qkv[((size_t)(b * T_ + k0 + r) * 3 + 1) * D_ + h * 64 + d];
    }
    __syncthreads();

    float acc[4][4] = {};
    #pragma unroll 8
    for (int d = 0; d < 64; d++) {
        float a[4], bb[4];
        #pragma unroll
        for (int i = 0; i < 4; i++) a[i] = Qs[d][ty * 4 + i];
        #pragma unroll
        for (int j = 0; j < 4; j++) bb[j] = Ks[d][tx * 4 + j];
        #pragma unroll
        for (int i = 0; i < 4; i++)
            #pragma unroll
            for (int j = 0; j < 4; j++)
                acc[i][j] += a[i] * bb[j];
    }

    #pragma unroll
    for (int i = 0; i < 4; i++) {
        int qi = q0 + ty * 4 + i;
        #pragma unroll
        for (int j = 0; j < 4; j++) {
            int kj = k0 + tx * 4 + j;
            int r = kj - qi;
            r = min(max(r, -MREL), MREL) + MREL;
            scores[((size_t)bh * T_ + qi) * T_ + kj] = acc[i][j] * 0.125f + relb[r * H_ + h];
        }
    }
}

// ---------------- softmax over rows of length T ----------------
__global__ void __launch_bounds__(256) softmax_kernel(float* __restrict__ scores)
{
    size_t row = blockIdx.x;
    float* r = scores + row * (size_t)T_;
    float v[4];
    float mx = -1e30f;
    #pragma unroll
    for (int j = 0; j < 4; j++) { v[j] = r[threadIdx.x + j * 256]; mx = fmaxf(mx, v[j]); }
    mx = block_reduce_max(mx);
    float s = 0.f;
    #pragma unroll
    for (int j = 0; j < 4; j++) { v[j] = __expf(v[j] - mx); s += v[j]; }
    s = block_reduce_sum(s);
    float inv = 1.0f / s;
    #pragma unroll
    for (int j = 0; j < 4; j++) r[threadIdx.x + j * 256] = v[j] * inv;
}

// ---------------- out = attn @ V  (writes (B,T,H*HD) layout) ----------------
__global__ void __launch_bounds__(256) av_kernel(
    const float* __restrict__ scores, const float* __restrict__ qkv,
    float* __restrict__ out)
{
    __shared__ float Ss[64][65];
    __shared__ float Vs[64][65];
    int bh = blockIdx.y, b = bh >> 4, h = bh & 15;
    int q0 = blockIdx.x * 64;
    int tid = threadIdx.x, tx = tid & 15, ty = tid >> 4;

    float acc[4][4] = {};
    for (int kt = 0; kt < T_; kt += 64) {
        #pragma unroll
        for (int j = 0; j < 16; j++) {
            int i = tid + j * 256;
            int r = i >> 6, c = i & 63;
            Ss[c][r] = scores[((size_t)bh * T_ + q0 + r) * T_ + kt + c];
            Vs[r][c] = qkv[((size_t)(b * T_ + kt + r) * 3 + 2) * D_ + h * 64 + c];
        }
        __syncthreads();
        #pragma unroll 8
        for (int k = 0; k < 64; k++) {
            float a[4], bb[4];
            #pragma unroll
            for (int i = 0; i < 4; i++) a[i] = Ss[k][ty * 4 + i];
            #pragma unroll
            for (int j = 0; j < 4; j++) bb[j] = Vs[k][tx * 4 + j];
            #pragma unroll
            for (int i = 0; i < 4; i++)
                #pragma unroll
                for (int j = 0; j < 4; j++)
                    acc[i][j] += a[i] * bb[j];
        }
        __syncthreads();
    }
    #pragma unroll
    for (int i = 0; i < 4; i++) {
        int q = q0 + ty * 4 + i;
        #pragma unroll
        for (int j = 0; j < 4; j++) {
            out[(size_t)(b * T_ + q) * D_ + h * 64 + tx * 4 + j] = acc[i][j];
        }
    }
}

// ---------------- GeGLU: ffact = a * gelu_exact(gate) ----------------
__global__ void __launch_bounds__(256) geglu_kernel(
    const float* __restrict__ ff1, float* __restrict__ ffact)
{
    int idx = blockIdx.x * 256 + threadIdx.x;   // BT * FF
    int m = idx >> 12;          // FF = 4096
    int f = idx & 4095;
    float a = ff1[(size_t)m * (2 * FF_) + f];
    float g = ff1[(size_t)m * (2 * FF_) + FF_ + f];
    float ge = 0.5f * g * (1.0f + erff(g * 0.70710678118654752f));
    ffact[idx] = a * ge;
}

// ---------------- final scaling epilogue ----------------
__global__ void __launch_bounds__(256) final_kernel(
    const float* __restrict__ o, const float* __restrict__ alpha,
    const float* __restrict__ beta, const float* __restrict__ alpha_scale,
    const float* __restrict__ beta_scale, float* __restrict__ out)
{
    int row = blockIdx.x;
    const float* orow = o + (size_t)row * D_;
    float v[4];
    float ss = 0.f;
    #pragma unroll
    for (int j = 0; j < 4; j++) { v[j] = orow[threadIdx.x + j * 256]; ss += v[j] * v[j]; }
    ss = block_reduce_sum(ss);
    float ms = sqrtf(ss);
    float a_s = fminf(fmaxf(alpha_scale[0], 0.f), 1.f);
    float sc = 1.0f + alpha[0] * a_s * fminf(ms, 5.0f);
    float bb = beta[0] * beta_scale[0];
    #pragma unroll
    for (int j = 0; j < 4; j++) {
        int c = threadIdx.x + j * 256;
        float val = v[j] * sc + bb;
        val = fminf(fmaxf(val, -10.0f), 10.0f);
        out[(size_t)row * D_ + c] = val + v[j];
    }
}

// ---------------- launch ----------------
extern "C" void kernel_launch(void* const* d_in, const int* in_sizes, int n_in,
                              void* d_out, int out_size)
{
    const float* x           = (const float*)d_in[0];
    const float* context     = (const float*)d_in[1];
    const float* W_in        = (const float*)d_in[2];
    const float* b_in        = (const float*)d_in[3];
    const float* ln_in_g     = (const float*)d_in[4];
    const float* ln_in_b     = (const float*)d_in[5];
    const float* ln1_g       = (const float*)d_in[6];
    const float* ln1_b       = (const float*)d_in[7];
    const float* Wqkv        = (const float*)d_in[8];
    const float* bqkv        = (const float*)d_in[9];
    const float* Wproj       = (const float*)d_in[10];
    const float* bproj       = (const float*)d_in[11];
    const float* rel_bias    = (const float*)d_in[12];
    const float* ln2_g       = (const float*)d_in[13];
    const float* ln2_b       = (const float*)d_in[14];
    const float* Wfc1        = (const float*)d_in[15];
    const float* bfc1        = (const float*)d_in[16];
    const float* Wfc2        = (const float*)d_in[17];
    const float* bfc2        = (const float*)d_in[18];
    const float* ln_f_g      = (const float*)d_in[19];
    const float* ln_f_b      = (const float*)d_in[20];
    const float* W_out       = (const float*)d_in[21];
    const float* b_out       = (const float*)d_in[22];
    const float* alpha       = (const float*)d_in[23];
    const float* beta        = (const float*)d_in[24];
    const float* alpha_scale = (const float*)d_in[25];
    const float* beta_scale  = (const float*)d_in[26];
    float* out = (float*)d_out;

    float *h, *hn, *tmp, *qkv, *scores, *attnout, *ff1, *ffact;
    cudaGetSymbolAddress((void**)&h,       g_h);
    cudaGetSymbolAddress((void**)&hn,      g_hn);
    cudaGetSymbolAddress((void**)&tmp,     g_tmp);
    cudaGetSymbolAddress((void**)&qkv,     g_qkv);
    cudaGetSymbolAddress((void**)&scores,  g_scores);
    cudaGetSymbolAddress((void**)&attnout, g_attnout);
    cudaGetSymbolAddress((void**)&ff1,     g_ff1);
    cudaGetSymbolAddress((void**)&ffact,   g_ffact);

    cudaFuncSetAttribute(gemm_mma<true>,  cudaFuncAttributeMaxDynamicSharedMemorySize, G_SMEM_BYTES);
    cudaFuncSetAttribute(gemm_mma<false>, cudaFuncAttributeMaxDynamicSharedMemorySize, G_SMEM_BYTES);

    // pre: h = LN(x @ W_in + b_in + context)
    gemm_mma<true><<<dim3(D_/BN, BT_/BM), 256, G_SMEM_BYTES>>>(
        x, W_in, b_in, context, tmp, BT_, D_, D_);
    ln_kernel<<<BT_, 256>>>(tmp, ln_in_g, ln_in_b, h);

    for (int l = 0; l < L_; l++) {
        // attention block
        ln_kernel<<<BT_, 256>>>(h, ln1_g + l*D_, ln1_b + l*D_, hn);
        gemm_mma<false><<<dim3(3*D_/BN, BT_/BM), 256, G_SMEM_BYTES>>>(
            hn, Wqkv + (size_t)l*D_*3*D_, bqkv + l*3*D_, nullptr, qkv, BT_, 3*D_, D_);
        rope_kernel<<<(B_*T_*H_*32)/256, 256>>>(qkv);
        score_kernel<<<dim3(T_/64, T_/64, B_*H_), 256>>>(
            qkv, rel_bias + (size_t)l*(2*MREL+1)*H_, scores);
        softmax_kernel<<<B_*H_*T_, 256>>>(scores);
        av_kernel<<<dim3(T_/64, B_*H_), 256>>>(scores, qkv, attnout);
        gemm_mma<true><<<dim3(D_/BN, BT_/BM), 256, G_SMEM_BYTES>>>(
            attnout, Wproj + (size_t)l*D_*D_, bproj + l*D_, h, h, BT_, D_, D_);

        // FFN block (GeGLU)
        ln_kernel<<<BT_, 256>>>(h, ln2_g + l*D_, ln2_b + l*D_, hn);
        gemm_mma<false><<<dim3(2*FF_/BN, BT_/BM), 256, G_SMEM_BYTES>>>(
            hn, Wfc1 + (size_t)l*D_*2*FF_, bfc1 + l*2*FF_, nullptr, ff1, BT_, 2*FF_, D_);
        geglu_kernel<<<(BT_*FF_)/256, 256>>>(ff1, ffact);
        gemm_mma<true><<<dim3(D_/BN, BT_/BM), 256, G_SMEM_BYTES>>>(
            ffact, Wfc2 + (size_t)l*(size_t)FF_*D_, bfc2 + l*D_, h, h, BT_, D_, FF_);
    }

    // post: o = LN(h) @ W_out + b_out, then the norm/clip epilogue
    ln_kernel<<<BT_, 256>>>(h, ln_f_g, ln_f_b, hn);
    gemm_mma<false><<<dim3(D_/BN, BT_/BM), 256, G_SMEM_BYTES>>>(
        hn, W_out, b_out, nullptr, tmp, BT_, D_, D_);
    final_kernel<<<BT_, 256>>>(tmp, alpha, beta, alpha_scale, beta_scale, out);
}

// round 7
// speedup vs baseline: 1.6996x; 1.2436x over previous
#include <cuda_runtime.h>
#include <cuda_bf16.h>
#include <math.h>
#include <stdint.h>

#define B_  2
#define T_  1024
#define D_  1024
#define H_  16
#define HD_ 64
#define FF_ 4096
#define L_  4
#define MREL 128
#define BT_ (B_*T_)   // 2048

// ---------------- scratch (no allocs allowed) ----------------
__device__ float g_h[BT_*D_];          // 8 MB
__device__ float g_hn[BT_*D_];         // 8 MB
__device__ float g_tmp[BT_*D_];        // 8 MB
__device__ float g_qkv[BT_*3*D_];      // 24 MB
__device__ float g_scores[(size_t)B_*H_*T_*T_]; // 128 MB
__device__ float g_attnout[BT_*D_];    // 8 MB
__device__ float g_ff1[BT_*2*FF_];     // 64 MB
__device__ float g_ffact[BT_*FF_];     // 32 MB

// bf16x2-packed activations (hi/lo), max M*K = 2048*4096
__device__ uint32_t g_ah[(size_t)BT_*FF_/2];   // 16.8 MB
__device__ uint32_t g_al[(size_t)BT_*FF_/2];

// bf16x2-packed weights (hi/lo), word layout [K/2][N]
#define WOFF_IN   ((size_t)0)
#define WSZ_IN    ((size_t)D_*D_/2)
#define WOFF_QKV  (WOFF_IN + WSZ_IN)
#define WSZ_QKV   ((size_t)D_*3*D_/2)
#define WOFF_PROJ (WOFF_QKV + L_*WSZ_QKV)
#define WSZ_PROJ  ((size_t)D_*D_/2)
#define WOFF_FC1  (WOFF_PROJ + L_*WSZ_PROJ)
#define WSZ_FC1   ((size_t)D_*2*FF_/2)
#define WOFF_FC2  (WOFF_FC1 + L_*WSZ_FC1)
#define WSZ_FC2   ((size_t)FF_*D_/2)
#define WOFF_OUT  (WOFF_FC2 + L_*WSZ_FC2)
#define WTOT      (WOFF_OUT + (size_t)D_*D_/2)
__device__ uint32_t g_wh[WTOT];        // ~138 MB
__device__ uint32_t g_wl[WTOT];        // ~138 MB

// ---------------- helpers ----------------
__device__ __forceinline__ uint32_t smem_u32(const void* p) {
    uint32_t a;
    asm("{ .reg .u64 t; cvta.to.shared.u64 t, %1; cvt.u32.u64 %0, t; }" : "=r"(a) : "l"(p));
    return a;
}
__device__ __forceinline__ uint32_t pack_hi(float a, float b, float& ra, float& rb) {
    __nv_bfloat16 ba = __float2bfloat16_rn(a), bb = __float2bfloat16_rn(b);
    ra = a - __bfloat162float(ba);
    rb = b - __bfloat162float(bb);
    uint16_t ua = *(uint16_t*)&ba, ub = *(uint16_t*)&bb;
    return (uint32_t)ua | ((uint32_t)ub << 16);
}
__device__ __forceinline__ uint32_t pack_lo(float ra, float rb) {
    __nv_bfloat16 ba = __float2bfloat16_rn(ra), bb = __float2bfloat16_rn(rb);
    uint16_t ua = *(uint16_t*)&ba, ub = *(uint16_t*)&bb;
    return (uint32_t)ua | ((uint32_t)ub << 16);
}
__device__ __forceinline__ void cp16(uint32_t dst, const void* src) {
    asm volatile("cp.async.cg.shared.global [%0], [%1], 16;" :: "r"(dst), "l"(src));
}
#define CP_COMMIT() asm volatile("cp.async.commit_group;" ::: "memory")
#define CP_WAIT1()  asm volatile("cp.async.wait_group 1;" ::: "memory")

__device__ __forceinline__ void mma_bf16(float c[4], const uint32_t a[4], const uint32_t b[2]) {
    asm volatile(
        "mma.sync.aligned.m16n8k16.row.col.f32.bf16.bf16.f32 "
        "{%0,%1,%2,%3}, {%4,%5,%6,%7}, {%8,%9}, {%0,%1,%2,%3};"
        : "+f"(c[0]), "+f"(c[1]), "+f"(c[2]), "+f"(c[3])
        : "r"(a[0]), "r"(a[1]), "r"(a[2]), "r"(a[3]), "r"(b[0]), "r"(b[1]));
}

// ---------------- operand conversion kernels ----------------
// Weights: W fp32 [K][N] -> hi/lo bf16x2 words [K/2][N]; blockIdx.y = layer slice.
__global__ void __launch_bounds__(256) convw_kernel(
    const float* __restrict__ W, uint32_t* __restrict__ hi, uint32_t* __restrict__ lo,
    int K, int N)
{
    size_t slice = (size_t)blockIdx.y;
    const float* Wp = W + slice * K * N;
    uint32_t* hp = hi + slice * (K/2) * N;
    uint32_t* lp = lo + slice * (K/2) * N;
    int w = blockIdx.x * 256 + threadIdx.x;    // word index in [K/2 * N)
    int n = w % N, k2 = w / N;
    float a = Wp[(size_t)(2*k2) * N + n];
    float b = Wp[(size_t)(2*k2+1) * N + n];
    float ra, rb;
    hp[w] = pack_hi(a, b, ra, rb);
    lp[w] = pack_lo(ra, rb);
}

// Activations: A fp32 [M][K] -> hi/lo bf16x2 words [M][K/2]
__global__ void __launch_bounds__(256) conva_kernel(
    const float* __restrict__ A, uint32_t* __restrict__ hi, uint32_t* __restrict__ lo,
    int K2)
{
    int w = blockIdx.x * 256 + threadIdx.x;
    int k2 = w % K2, m = w / K2;
    float2 v = *(const float2*)(A + (size_t)m * (2*K2) + 2*k2);
    float ra, rb;
    hi[w] = pack_hi(v.x, v.y, ra, rb);
    lo[w] = pack_lo(ra, rb);
}

// ================= bf16x3 mma.sync GEMM =================
// C[M,N] = A[M,K] @ W[K,N] + bias (+ Res).  Operands pre-packed bf16x2 hi/lo.
// CTA 128x256, 8 warps (2x4), warp tile 64x64, BK=32, 3-stage cp.async pipeline.
#define BM 128
#define BN 256
#define BK 32
#define KP 20                      // A smem words per m-row (16 + 4 pad)
#define BPAD 264                   // B smem words per k2-row (256 + 8 pad)
#define A_STG (BM*KP)              // 2560 words
#define B_STG (16*BPAD)            // 4224 words
#define STG_W (2*A_STG + 2*B_STG)  // 13568 words / stage
#define NSTAGE 3
#define G_SMEM_BYTES (NSTAGE*STG_W*4)   // 162816 B

template<bool HAS_RES>
__global__ void __launch_bounds__(256, 1) gemm_bf16x3(
    const uint32_t* __restrict__ Ah, const uint32_t* __restrict__ Al,
    const uint32_t* __restrict__ Wh, const uint32_t* __restrict__ Wl,
    const float* __restrict__ bias, const float* __restrict__ Res,
    float* __restrict__ C, int M, int N, int K)
{
    extern __shared__ uint32_t sm[];
    const uint32_t smem_base = smem_u32(sm);

    const int tid = threadIdx.x;
    const int lane = tid & 31, wid = tid >> 5;
    const int wm = wid >> 2, wn = wid & 3;          // 2 x 4 warp grid
    const int m0 = blockIdx.y * BM, n0 = blockIdx.x * BN;
    const int r = lane >> 2, cq = lane & 3;
    const int K2 = K >> 1;

    float acc[4][8][4];
    #pragma unroll
    for (int i = 0; i < 4; i++)
        #pragma unroll
        for (int j = 0; j < 8; j++)
            #pragma unroll
            for (int q = 0; q < 4; q++) acc[i][j][q] = 0.f;

    // cp.async mappings
    const int am = tid & 127, aqh = tid >> 7;       // A: row, quad-half
    const int nq = tid & 63, k2b = tid >> 6;        // B: n-quad, k2 base

    auto issue_loads = [&](int c, int s) {
        const int kc2 = c * 16;
        const uint32_t base = smem_base + (uint32_t)s * STG_W * 4;
        #pragma unroll
        for (int j = 0; j < 2; j++) {
            int q = aqh * 2 + j;
            const uint32_t* srcH = Ah + (size_t)(m0 + am) * K2 + kc2 + 4*q;
            const uint32_t* srcL = Al + (size_t)(m0 + am) * K2 + kc2 + 4*q;
            cp16(base + (uint32_t)(am*KP + 4*q)*4, srcH);
            cp16(base + (uint32_t)(A_STG + am*KP + 4*q)*4, srcL);
        }
        #pragma unroll
        for (int j = 0; j < 4; j++) {
            int k2 = k2b + 4*j;
            const uint32_t* srcH = Wh + (size_t)(kc2 + k2) * N + n0 + 4*nq;
            const uint32_t* srcL = Wl + (size_t)(kc2 + k2) * N + n0 + 4*nq;
            cp16(base + (uint32_t)(2*A_STG + k2*BPAD + 4*nq)*4, srcH);
            cp16(base + (uint32_t)(2*A_STG + B_STG + k2*BPAD + 4*nq)*4, srcL);
        }
    };

    auto compute = [&](int s) {
        const uint32_t* AsH = sm + (size_t)s * STG_W;
        const uint32_t* AsL = AsH + A_STG;
        const uint32_t* BsH = AsH + 2*A_STG;
        const uint32_t* BsL = BsH + B_STG;
        #pragma unroll
        for (int ks = 0; ks < 2; ks++) {
            const int k2 = ks * 8 + cq;
            uint32_t ah[4][4], al[4][4], bh[8][2], bl[8][2];
            #pragma unroll
            for (int mt = 0; mt < 4; mt++) {
                int row = wm*64 + mt*16 + r;
                ah[mt][0] = AsH[row*KP + k2];
                ah[mt][1] = AsH[(row+8)*KP + k2];
                ah[mt][2] = AsH[row*KP + k2 + 4];
                ah[mt][3] = AsH[(row+8)*KP + k2 + 4];
                al[mt][0] = AsL[row*KP + k2];
                al[mt][1] = AsL[(row+8)*KP + k2];
                al[mt][2] = AsL[row*KP + k2 + 4];
                al[mt][3] = AsL[(row+8)*KP + k2 + 4];
            }
            #pragma unroll
            for (int nt = 0; nt < 8; nt++) {
                int n = wn*64 + nt*8 + r;
                bh[nt][0] = BsH[k2*BPAD + n];
                bh[nt][1] = BsH[(k2+4)*BPAD + n];
                bl[nt][0] = BsL[k2*BPAD + n];
                bl[nt][1] = BsL[(k2+4)*BPAD + n];
            }
            #pragma unroll
            for (int mt = 0; mt < 4; mt++)
                #pragma unroll
                for (int nt = 0; nt < 8; nt++) {
                    mma_bf16(acc[mt][nt], ah[mt], bl[nt]);
                    mma_bf16(acc[mt][nt], al[mt], bh[nt]);
                    mma_bf16(acc[mt][nt], ah[mt], bh[nt]);
                }
        }
    };

    const int NC = K / BK;
    issue_loads(0, 0); CP_COMMIT();
    issue_loads(1, 1); CP_COMMIT();

    for (int c = 0; c < NC; c++) {
        CP_WAIT1();
        __syncthreads();
        if (c + 2 < NC) issue_loads(c + 2, (c + 2) % NSTAGE);
        CP_COMMIT();
        compute(c % NSTAGE);
    }

    // epilogue
    const int cb = cq * 2;
    #pragma unroll
    for (int mt = 0; mt < 4; mt++) {
        #pragma unroll
        for (int nt = 0; nt < 8; nt++) {
            int m = m0 + wm*64 + mt*16 + r;
            int n = n0 + wn*64 + nt*8 + cb;
            float2 bv = *(const float2*)(bias + n);
            float2 v0, v1;
            v0.x = acc[mt][nt][0] + bv.x; v0.y = acc[mt][nt][1] + bv.y;
            v1.x = acc[mt][nt][2] + bv.x; v1.y = acc[mt][nt][3] + bv.y;
            if (HAS_RES) {
                float2 r0 = *(const float2*)(Res + (size_t)m * N + n);
                float2 r1 = *(const float2*)(Res + (size_t)(m + 8) * N + n);
                v0.x += r0.x; v0.y += r0.y; v1.x += r1.x; v1.y += r1.y;
            }
            *(float2*)(C + (size_t)m * N + n) = v0;
            *(float2*)(C + (size_t)(m + 8) * N + n) = v1;
        }
    }
}

// ---------------- block reductions ----------------
__device__ __forceinline__ float block_reduce_sum(float v) {
    __shared__ float sh[33];
    int lane = threadIdx.x & 31, wid = threadIdx.x >> 5;
    #pragma unroll
    for (int o = 16; o > 0; o >>= 1) v += __shfl_xor_sync(0xffffffffu, v, o);
    if (lane == 0) sh[wid] = v;
    __syncthreads();
    if (wid == 0) {
        float t = (lane < 8) ? sh[lane] : 0.f;
        #pragma unroll
        for (int o = 4; o > 0; o >>= 1) t += __shfl_xor_sync(0xffffffffu, t, o);
        if (lane == 0) sh[32] = t;
    }
    __syncthreads();
    return sh[32];
}

__device__ __forceinline__ float block_reduce_max(float v) {
    __shared__ float sh[33];
    int lane = threadIdx.x & 31, wid = threadIdx.x >> 5;
    #pragma unroll
    for (int o = 16; o > 0; o >>= 1) v = fmaxf(v, __shfl_xor_sync(0xffffffffu, v, o));
    if (lane == 0) sh[wid] = v;
    __syncthreads();
    if (wid == 0) {
        float t = (lane < 8) ? sh[lane] : -1e30f;
        #pragma unroll
        for (int o = 4; o > 0; o >>= 1) t = fmaxf(t, __shfl_xor_sync(0xffffffffu, t, o));
        if (lane == 0) sh[32] = t;
    }
    __syncthreads();
    return sh[32];
}

// ---------------- LayerNorm over rows of D ----------------
__global__ void __launch_bounds__(256) ln_kernel(
    const float* __restrict__ x, const float* __restrict__ g,
    const float* __restrict__ b, float* __restrict__ y)
{
    int row = blockIdx.x;
    const float* xr = x + (size_t)row * D_;
    float v[4];
    float s = 0.f;
    #pragma unroll
    for (int j = 0; j < 4; j++) { v[j] = xr[threadIdx.x + j * 256]; s += v[j]; }
    float mean = block_reduce_sum(s) * (1.0f / D_);
    float var = 0.f;
    #pragma unroll
    for (int j = 0; j < 4; j++) { float d0 = v[j] - mean; var += d0 * d0; }
    var = block_reduce_sum(var) * (1.0f / D_);
    float rstd = rsqrtf(var + 1e-5f);
    float* yr = y + (size_t)row * D_;
    #pragma unroll
    for (int j = 0; j < 4; j++) {
        int c = threadIdx.x + j * 256;
        yr[c] = (v[j] - mean) * rstd * g[c] + b[c];
    }
}

// ---------------- RoPE (in-place on q and k parts of qkv) ----------------
__global__ void __launch_bounds__(256) rope_kernel(float* __restrict__ qkv)
{
    int idx = blockIdx.x * 256 + threadIdx.x;  // B*T*H*32
    int p = idx & 31;
    int h = (idx >> 5) & 15;
    int t = (idx >> 9) & 1023;
    int b = idx >> 19;
    int ifx = (2 * p) & 31;
    float theta = (float)t * powf(10000.0f, -(float)(2 * ifx) * (1.0f / 64.0f));
    float s, c;
    sincosf(theta, &s, &c);
    size_t baseq = ((size_t)(b * T_ + t) * 3 + 0) * D_ + h * 64 + 2 * p;
    size_t basek = baseq + D_;
    float x1 = qkv[baseq], x2 = qkv[baseq + 1];
    qkv[baseq]     = x1 * c - x2 * s;
    qkv[baseq + 1] = x1 * s + x2 * c;
    x1 = qkv[basek]; x2 = qkv[basek + 1];
    qkv[basek]     = x1 * c - x2 * s;
    qkv[basek + 1] = x1 * s + x2 * c;
}

// ---------------- scores = Q K^T * scale + rel_bias ----------------
__global__ void __launch_bounds__(256) score_kernel(
    const float* __restrict__ qkv, const float* __restrict__ relb,
    float* __restrict__ scores)
{
    __shared__ float Qs[64][65];
    __shared__ float Ks[64][65];
    int bh = blockIdx.z, b = bh >> 4, h = bh & 15;
    int q0 = blockIdx.y * 64, k0 = blockIdx.x * 64;
    int tid = threadIdx.x, tx = tid & 15, ty = tid >> 4;

    #pragma unroll
    for (int j = 0; j < 16; j++) {
        int i = tid + j * 256;
        int r = i >> 6, d = i & 63;
        Qs[d][r] = qkv[((size_t)(b * T_ + q0 + r) * 3 + 0) * D_ + h * 64 + d];
        Ks[d][r] = qkv[((size_t)(b * T_ + k0 + r) * 3 + 1) * D_ + h * 64 + d];
    }
    __syncthreads();

    float acc[4][4] = {};
    #pragma unroll 8
    for (int d = 0; d < 64; d++) {
        float a[4], bb[4];
        #pragma unroll
        for (int i = 0; i < 4; i++) a[i] = Qs[d][ty * 4 + i];
        #pragma unroll
        for (int j = 0; j < 4; j++) bb[j] = Ks[d][tx * 4 + j];
        #pragma unroll
        for (int i = 0; i < 4; i++)
            #pragma unroll
            for (int j = 0; j < 4; j++)
                acc[i][j] += a[i] * bb[j];
    }

    #pragma unroll
    for (int i = 0; i < 4; i++) {
        int qi = q0 + ty * 4 + i;
        #pragma unroll
        for (int j = 0; j < 4; j++) {
            int kj = k0 + tx * 4 + j;
            int rr = kj - qi;
            rr = min(max(rr, -MREL), MREL) + MREL;
            scores[((size_t)bh * T_ + qi) * T_ + kj] = acc[i][j] * 0.125f + relb[rr * H_ + h];
        }
    }
}

// ---------------- softmax over rows of length T ----------------
__global__ void __launch_bounds__(256) softmax_kernel(float* __restrict__ scores)
{
    size_t row = blockIdx.x;
    float* r = scores + row * (size_t)T_;
    float v[4];
    float mx = -1e30f;
    #pragma unroll
    for (int j = 0; j < 4; j++) { v[j] = r[threadIdx.x + j * 256]; mx = fmaxf(mx, v[j]); }
    mx = block_reduce_max(mx);
    float s = 0.f;
    #pragma unroll
    for (int j = 0; j < 4; j++) { v[j] = __expf(v[j] - mx); s += v[j]; }
    s = block_reduce_sum(s);
    float inv = 1.0f / s;
    #pragma unroll
    for (int j = 0; j < 4; j++) r[threadIdx.x + j * 256] = v[j] * inv;
}

// ---------------- out = attn @ V  (writes (B,T,H*HD) layout) ----------------
__global__ void __launch_bounds__(256) av_kernel(
    const float* __restrict__ scores, const float* __restrict__ qkv,
    float* __restrict__ out)
{
    __shared__ float Ss[64][65];
    __shared__ float Vs[64][65];
    int bh = blockIdx.y, b = bh >> 4, h = bh & 15;
    int q0 = blockIdx.x * 64;
    int tid = threadIdx.x, tx = tid & 15, ty = tid >> 4;

    float acc[4][4] = {};
    for (int kt = 0; kt < T_; kt += 64) {
        #pragma unroll
        for (int j = 0; j < 16; j++) {
            int i = tid + j * 256;
            int r = i >> 6, c = i & 63;
            Ss[c][r] = scores[((size_t)bh * T_ + q0 + r) * T_ + kt + c];
            Vs[r][c] = qkv[((size_t)(b * T_ + kt + r) * 3 + 2) * D_ + h * 64 + c];
        }
        __syncthreads();
        #pragma unroll 8
        for (int k = 0; k < 64; k++) {
            float a[4], bb[4];
            #pragma unroll
            for (int i = 0; i < 4; i++) a[i] = Ss[k][ty * 4 + i];
            #pragma unroll
            for (int j = 0; j < 4; j++) bb[j] = Vs[k][tx * 4 + j];
            #pragma unroll
            for (int i = 0; i < 4; i++)
                #pragma unroll
                for (int j = 0; j < 4; j++)
                    acc[i][j] += a[i] * bb[j];
        }
        __syncthreads();
    }
    #pragma unroll
    for (int i = 0; i < 4; i++) {
        int q = q0 + ty * 4 + i;
        #pragma unroll
        for (int j = 0; j < 4; j++) {
            out[(size_t)(b * T_ + q) * D_ + h * 64 + tx * 4 + j] = acc[i][j];
        }
    }
}

// ---------------- GeGLU: ffact = a * gelu_exact(gate) ----------------
__global__ void __launch_bounds__(256) geglu_kernel(
    const float* __restrict__ ff1, float* __restrict__ ffact)
{
    int idx = blockIdx.x * 256 + threadIdx.x;   // BT * FF
    int m = idx >> 12;          // FF = 4096
    int f = idx & 4095;
    float a = ff1[(size_t)m * (2 * FF_) + f];
    float g = ff1[(size_t)m * (2 * FF_) + FF_ + f];
    float ge = 0.5f * g * (1.0f + erff(g * 0.70710678118654752f));
    ffact[idx] = a * ge;
}

// ---------------- final scaling epilogue ----------------
__global__ void __launch_bounds__(256) final_kernel(
    const float* __restrict__ o, const float* __restrict__ alpha,
    const float* __restrict__ beta, const float* __restrict__ alpha_scale,
    const float* __restrict__ beta_scale, float* __restrict__ out)
{
    int row = blockIdx.x;
    const float* orow = o + (size_t)row * D_;
    float v[4];
    float ss = 0.f;
    #pragma unroll
    for (int j = 0; j < 4; j++) { v[j] = orow[threadIdx.x + j * 256]; ss += v[j] * v[j]; }
    ss = block_reduce_sum(ss);
    float ms = sqrtf(ss);
    float a_s = fminf(fmaxf(alpha_scale[0], 0.f), 1.f);
    float sc = 1.0f + alpha[0] * a_s * fminf(ms, 5.0f);
    float bb = beta[0] * beta_scale[0];
    #pragma unroll
    for (int j = 0; j < 4; j++) {
        int c = threadIdx.x + j * 256;
        float val = v[j] * sc + bb;
        val = fminf(fmaxf(val, -10.0f), 10.0f);
        out[(size_t)row * D_ + c] = val + v[j];
    }
}

// ---------------- launch ----------------
extern "C" void kernel_launch(void* const* d_in, const int* in_sizes, int n_in,
                              void* d_out, int out_size)
{
    const float* x           = (const float*)d_in[0];
    const float* context     = (const float*)d_in[1];
    const float* W_in        = (const float*)d_in[2];
    const float* b_in        = (const float*)d_in[3];
    const float* ln_in_g     = (const float*)d_in[4];
    const float* ln_in_b     = (const float*)d_in[5];
    const float* ln1_g       = (const float*)d_in[6];
    const float* ln1_b       = (const float*)d_in[7];
    const float* Wqkv        = (const float*)d_in[8];
    const float* bqkv        = (const float*)d_in[9];
    const float* Wproj       = (const float*)d_in[10];
    const float* bproj       = (const float*)d_in[11];
    const float* rel_bias    = (const float*)d_in[12];
    const float* ln2_g       = (const float*)d_in[13];
    const float* ln2_b       = (const float*)d_in[14];
    const float* Wfc1        = (const float*)d_in[15];
    const float* bfc1        = (const float*)d_in[16];
    const float* Wfc2        = (const float*)d_in[17];
    const float* bfc2        = (const float*)d_in[18];
    const float* ln_f_g      = (const float*)d_in[19];
    const float* ln_f_b      = (const float*)d_in[20];
    const float* W_out       = (const float*)d_in[21];
    const float* b_out       = (const float*)d_in[22];
    const float* alpha       = (const float*)d_in[23];
    const float* beta        = (const float*)d_in[24];
    const float* alpha_scale = (const float*)d_in[25];
    const float* beta_scale  = (const float*)d_in[26];
    float* out = (float*)d_out;

    float *h, *hn, *tmp, *qkv, *scores, *attnout, *ff1, *ffact;
    uint32_t *ah, *al, *wh, *wl;
    cudaGetSymbolAddress((void**)&h,       g_h);
    cudaGetSymbolAddress((void**)&hn,      g_hn);
    cudaGetSymbolAddress((void**)&tmp,     g_tmp);
    cudaGetSymbolAddress((void**)&qkv,     g_qkv);
    cudaGetSymbolAddress((void**)&scores,  g_scores);
    cudaGetSymbolAddress((void**)&attnout, g_attnout);
    cudaGetSymbolAddress((void**)&ff1,     g_ff1);
    cudaGetSymbolAddress((void**)&ffact,   g_ffact);
    cudaGetSymbolAddress((void**)&ah,      g_ah);
    cudaGetSymbolAddress((void**)&al,      g_al);
    cudaGetSymbolAddress((void**)&wh,      g_wh);
    cudaGetSymbolAddress((void**)&wl,      g_wl);

    cudaFuncSetAttribute(gemm_bf16x3<true>,  cudaFuncAttributeMaxDynamicSharedMemorySize, G_SMEM_BYTES);
    cudaFuncSetAttribute(gemm_bf16x3<false>, cudaFuncAttributeMaxDynamicSharedMemorySize, G_SMEM_BYTES);

    // ---- weight pre-conversion (hi/lo bf16x2 words) ----
    convw_kernel<<<dim3((int)(WSZ_IN/256), 1),   256>>>(W_in,  wh + WOFF_IN,   wl + WOFF_IN,   D_,  D_);
    convw_kernel<<<dim3((int)(WSZ_QKV/256), L_), 256>>>(Wqkv,  wh + WOFF_QKV,  wl + WOFF_QKV,  D_,  3*D_);
    convw_kernel<<<dim3((int)(WSZ_PROJ/256), L_),256>>>(Wproj, wh + WOFF_PROJ, wl + WOFF_PROJ, D_,  D_);
    convw_kernel<<<dim3((int)(WSZ_FC1/256), L_), 256>>>(Wfc1,  wh + WOFF_FC1,  wl + WOFF_FC1,  D_,  2*FF_);
    convw_kernel<<<dim3((int)(WSZ_FC2/256), L_), 256>>>(Wfc2,  wh + WOFF_FC2,  wl + WOFF_FC2,  FF_, D_);
    convw_kernel<<<dim3((int)(WSZ_IN/256), 1),   256>>>(W_out, wh + WOFF_OUT,  wl + WOFF_OUT,  D_,  D_);

    #define CONV_A(src, K) conva_kernel<<<(BT_*(K)/2)/256, 256>>>((src), ah, al, (K)/2)
    #define GEMM(RES, N, K, WOFF, bias, res, dst) \
        gemm_bf16x3<RES><<<dim3((N)/BN, BT_/BM), 256, G_SMEM_BYTES>>>( \
            ah, al, wh + (WOFF), wl + (WOFF), (bias), (res), (dst), BT_, (N), (K))

    // pre: h = LN(x @ W_in + b_in + context)
    CONV_A(x, D_);
    GEMM(true, D_, D_, WOFF_IN, b_in, context, tmp);
    ln_kernel<<<BT_, 256>>>(tmp, ln_in_g, ln_in_b, h);

    for (int l = 0; l < L_; l++) {
        // attention block
        ln_kernel<<<BT_, 256>>>(h, ln1_g + l*D_, ln1_b + l*D_, hn);
        CONV_A(hn, D_);
        GEMM(false, 3*D_, D_, WOFF_QKV + (size_t)l*WSZ_QKV, bqkv + l*3*D_, nullptr, qkv);
        rope_kernel<<<(B_*T_*H_*32)/256, 256>>>(qkv);
        score_kernel<<<dim3(T_/64, T_/64, B_*H_), 256>>>(
            qkv, rel_bias + (size_t)l*(2*MREL+1)*H_, scores);
        softmax_kernel<<<B_*H_*T_, 256>>>(scores);
        av_kernel<<<dim3(T_/64, B_*H_), 256>>>(scores, qkv, attnout);
        CONV_A(attnout, D_);
        GEMM(true, D_, D_, WOFF_PROJ + (size_t)l*WSZ_PROJ, bproj + l*D_, h, h);

        // FFN block (GeGLU)
        ln_kernel<<<BT_, 256>>>(h, ln2_g + l*D_, ln2_b + l*D_, hn);
        CONV_A(hn, D_);
        GEMM(false, 2*FF_, D_, WOFF_FC1 + (size_t)l*WSZ_FC1, bfc1 + l*2*FF_, nullptr, ff1);
        geglu_kernel<<<(BT_*FF_)/256, 256>>>(ff1, ffact);
        CONV_A(ffact, FF_);
        GEMM(true, D_, FF_, WOFF_FC2 + (size_t)l*WSZ_FC2, bfc2 + l*D_, h, h);
    }

    // post: o = LN(h) @ W_out + b_out, then the norm/clip epilogue
    ln_kernel<<<BT_, 256>>>(h, ln_f_g, ln_f_b, hn);
    CONV_A(hn, D_);
    GEMM(false, D_, D_, WOFF_OUT, b_out, nullptr, tmp);
    final_kernel<<<BT_, 256>>>(tmp, alpha, beta, alpha_scale, beta_scale, out);
}

// round 9
// speedup vs baseline: 2.2140x; 1.3027x over previous
#include <cuda_runtime.h>
#include <cuda_bf16.h>
#include <math.h>
#include <stdint.h>

#define B_  2
#define T_  1024
#define D_  1024
#define H_  16
#define HD_ 64
#define FF_ 4096
#define L_  4
#define MREL 128
#define BT_ (B_*T_)   // 2048

// ---------------- scratch (no allocs allowed) ----------------
__device__ float g_h[BT_*D_];          // 8 MB
__device__ float g_tmp[BT_*D_];        // 8 MB
__device__ float g_qkv[BT_*3*D_];      // 24 MB
__device__ float g_ff1[BT_*2*FF_];     // 64 MB

// bf16x2-packed activations (hi/lo), max M*K = 2048*4096
__device__ uint32_t g_ah[(size_t)BT_*FF_/2];
__device__ uint32_t g_al[(size_t)BT_*FF_/2];

// attention operands, bf16x2 words
__device__ uint32_t g_qh[(size_t)B_*H_*T_*32];  // [bh][t][d2]
__device__ uint32_t g_ql[(size_t)B_*H_*T_*32];
__device__ uint32_t g_kh[(size_t)B_*H_*32*T_];  // [bh][d2][t]
__device__ uint32_t g_kl[(size_t)B_*H_*32*T_];
__device__ uint32_t g_vh[(size_t)B_*H_*512*64]; // [bh][t2][d]
__device__ uint32_t g_vl[(size_t)B_*H_*512*64];

// bf16x2-packed weights (hi/lo), word layout [K/2][N]
#define WOFF_IN   ((size_t)0)
#define WSZ_IN    ((size_t)D_*D_/2)
#define WOFF_QKV  (WOFF_IN + WSZ_IN)
#define WSZ_QKV   ((size_t)D_*3*D_/2)
#define WOFF_PROJ (WOFF_QKV + L_*WSZ_QKV)
#define WSZ_PROJ  ((size_t)D_*D_/2)
#define WOFF_FC1  (WOFF_PROJ + L_*WSZ_PROJ)
#define WSZ_FC1   ((size_t)D_*2*FF_/2)
#define WOFF_FC2  (WOFF_FC1 + L_*WSZ_FC1)
#define WSZ_FC2   ((size_t)FF_*D_/2)
#define WOFF_OUT  (WOFF_FC2 + L_*WSZ_FC2)
#define WTOT      (WOFF_OUT + (size_t)D_*D_/2)
__device__ uint32_t g_wh[WTOT];
__device__ uint32_t g_wl[WTOT];

// ---------------- helpers ----------------
__device__ __forceinline__ uint32_t smem_u32(const void* p) {
    uint32_t a;
    asm("{ .reg .u64 t; cvta.to.shared.u64 t, %1; cvt.u32.u64 %0, t; }" : "=r"(a) : "l"(p));
    return a;
}
__device__ __forceinline__ uint32_t pack_hi(float a, float b, float& ra, float& rb) {
    __nv_bfloat16 ba = __float2bfloat16_rn(a), bb = __float2bfloat16_rn(b);
    ra = a - __bfloat162float(ba);
    rb = b - __bfloat162float(bb);
    uint16_t ua = *(uint16_t*)&ba, ub = *(uint16_t*)&bb;
    return (uint32_t)ua | ((uint32_t)ub << 16);
}
__device__ __forceinline__ uint32_t pack_lo(float ra, float rb) {
    __nv_bfloat16 ba = __float2bfloat16_rn(ra), bb = __float2bfloat16_rn(rb);
    uint16_t ua = *(uint16_t*)&ba, ub = *(uint16_t*)&bb;
    return (uint32_t)ua | ((uint32_t)ub << 16);
}
__device__ __forceinline__ void cp16(uint32_t dst, const void* src) {
    asm volatile("cp.async.cg.shared.global [%0], [%1], 16;" :: "r"(dst), "l"(src));
}
#define CP_COMMIT() asm volatile("cp.async.commit_group;" ::: "memory")
#define CP_WAIT1()  asm volatile("cp.async.wait_group 1;" ::: "memory")
#define CP_WAIT0()  asm volatile("cp.async.wait_group 0;" ::: "memory")

__device__ __forceinline__ void mma_bf16(float c[4], const uint32_t a[4], const uint32_t b[2]) {
    asm volatile(
        "mma.sync.aligned.m16n8k16.row.col.f32.bf16.bf16.f32 "
        "{%0,%1,%2,%3}, {%4,%5,%6,%7}, {%8,%9}, {%0,%1,%2,%3};"
        : "+f"(c[0]), "+f"(c[1]), "+f"(c[2]), "+f"(c[3])
        : "r"(a[0]), "r"(a[1]), "r"(a[2]), "r"(a[3]), "r"(b[0]), "r"(b[1]));
}
__device__ __forceinline__ float qmax(float v) {
    v = fmaxf(v, __shfl_xor_sync(0xffffffffu, v, 1));
    v = fmaxf(v, __shfl_xor_sync(0xffffffffu, v, 2));
    return v;
}
__device__ __forceinline__ float qsum(float v) {
    v += __shfl_xor_sync(0xffffffffu, v, 1);
    v += __shfl_xor_sync(0xffffffffu, v, 2);
    return v;
}

// ---------------- conversion kernels ----------------
__global__ void __launch_bounds__(256) convw_kernel(
    const float* __restrict__ W, uint32_t* __restrict__ hi, uint32_t* __restrict__ lo,
    int K, int N)
{
    size_t slice = (size_t)blockIdx.y;
    const float* Wp = W + slice * K * N;
    uint32_t* hp = hi + slice * (K/2) * N;
    uint32_t* lp = lo + slice * (K/2) * N;
    int w = blockIdx.x * 256 + threadIdx.x;
    int n = w % N, k2 = w / N;
    float a = Wp[(size_t)(2*k2) * N + n];
    float b = Wp[(size_t)(2*k2+1) * N + n];
    float ra, rb;
    hp[w] = pack_hi(a, b, ra, rb);
    lp[w] = pack_lo(ra, rb);
}

__global__ void __launch_bounds__(256) conva_kernel(
    const float* __restrict__ A, uint32_t* __restrict__ hi, uint32_t* __restrict__ lo,
    int K2)
{
    int w = blockIdx.x * 256 + threadIdx.x;
    int k2 = w % K2, m = w / K2;
    float2 v = *(const float2*)(A + (size_t)m * (2*K2) + 2*k2);
    float ra, rb;
    hi[w] = pack_hi(v.x, v.y, ra, rb);
    lo[w] = pack_lo(ra, rb);
}

// rope + pack qkv into attention layouts; idx space = B*H*T*32 = 1M
__global__ void __launch_bounds__(256) ropeconv_kernel(
    const float* __restrict__ qkv,
    uint32_t* __restrict__ qh, uint32_t* __restrict__ ql,
    uint32_t* __restrict__ kh, uint32_t* __restrict__ kl,
    uint32_t* __restrict__ vh, uint32_t* __restrict__ vl)
{
    int idx = blockIdx.x * 256 + threadIdx.x;
    float ra, rb;
    // Q: (b, h, t, p), p inner
    {
        int p = idx & 31, t = (idx >> 5) & 1023, hh = (idx >> 15) & 15, b = idx >> 19;
        size_t src = ((size_t)(b*T_ + t)*3 + 0)*D_ + hh*64 + 2*p;
        float x1 = qkv[src], x2 = qkv[src+1];
        float theta = (float)t * powf(10000.f, -(float)(2*((2*p) & 31)) * (1.f/64.f));
        float sn, cs; sincosf(theta, &sn, &cs);
        float e = (x1*cs - x2*sn) * 0.125f;
        float o = (x1*sn + x2*cs) * 0.125f;
        size_t dst = ((size_t)(b*16 + hh)*T_ + t)*32 + p;
        qh[dst] = pack_hi(e, o, ra, rb); ql[dst] = pack_lo(ra, rb);
    }
    // K: (b, h, p, t), t inner -> transposed [d2][t]
    {
        int t = idx & 1023, p = (idx >> 10) & 31, hh = (idx >> 15) & 15, b = idx >> 19;
        size_t src = ((size_t)(b*T_ + t)*3 + 1)*D_ + hh*64 + 2*p;
        float x1 = qkv[src], x2 = qkv[src+1];
        float theta = (float)t * powf(10000.f, -(float)(2*((2*p) & 31)) * (1.f/64.f));
        float sn, cs; sincosf(theta, &sn, &cs);
        float e = x1*cs - x2*sn;
        float o = x1*sn + x2*cs;
        size_t dst = ((size_t)(b*16 + hh)*32 + p)*T_ + t;
        kh[dst] = pack_hi(e, o, ra, rb); kl[dst] = pack_lo(ra, rb);
    }
    // V: (b, h, t2, d), d inner -> [t2][d] pairs across t
    {
        int d = idx & 63, t2 = (idx >> 6) & 511, hh = (idx >> 15) & 15, b = idx >> 19;
        size_t s0 = ((size_t)(b*T_ + 2*t2)*3 + 2)*D_ + hh*64 + d;
        float v0 = qkv[s0], v1 = qkv[s0 + 3*D_];
        size_t dst = ((size_t)(b*16 + hh)*512 + t2)*64 + d;
        vh[dst] = pack_hi(v0, v1, ra, rb); vl[dst] = pack_lo(ra, rb);
    }
}

// ================= bf16x3 mma.sync GEMM =================
#define BM 128
#define BN 256
#define BK 32
#define KP 20
#define BPAD 264
#define A_STG (BM*KP)
#define B_STG (16*BPAD)
#define STG_W (2*A_STG + 2*B_STG)
#define NSTAGE 3
#define G_SMEM_BYTES (NSTAGE*STG_W*4)

template<bool HAS_RES>
__global__ void __launch_bounds__(256, 1) gemm_bf16x3(
    const uint32_t* __restrict__ Ah, const uint32_t* __restrict__ Al,
    const uint32_t* __restrict__ Wh, const uint32_t* __restrict__ Wl,
    const float* __restrict__ bias, const float* __restrict__ Res,
    float* __restrict__ C, int M, int N, int K)
{
    extern __shared__ uint32_t sm[];
    const uint32_t smem_base = smem_u32(sm);

    const int tid = threadIdx.x;
    const int lane = tid & 31, wid = tid >> 5;
    const int wm = wid >> 2, wn = wid & 3;
    const int m0 = blockIdx.y * BM, n0 = blockIdx.x * BN;
    const int r = lane >> 2, cq = lane & 3;
    const int K2 = K >> 1;

    float acc[4][8][4];
    #pragma unroll
    for (int i = 0; i < 4; i++)
        #pragma unroll
        for (int j = 0; j < 8; j++)
            #pragma unroll
            for (int q = 0; q < 4; q++) acc[i][j][q] = 0.f;

    const int am = tid & 127, aqh = tid >> 7;
    const int nq = tid & 63, k2b = tid >> 6;

    auto issue_loads = [&](int c, int s) {
        const int kc2 = c * 16;
        const uint32_t base = smem_base + (uint32_t)s * STG_W * 4;
        #pragma unroll
        for (int j = 0; j < 2; j++) {
            int q = aqh * 2 + j;
            cp16(base + (uint32_t)(am*KP + 4*q)*4, Ah + (size_t)(m0 + am) * K2 + kc2 + 4*q);
            cp16(base + (uint32_t)(A_STG + am*KP + 4*q)*4, Al + (size_t)(m0 + am) * K2 + kc2 + 4*q);
        }
        #pragma unroll
        for (int j = 0; j < 4; j++) {
            int k2 = k2b + 4*j;
            cp16(base + (uint32_t)(2*A_STG + k2*BPAD + 4*nq)*4, Wh + (size_t)(kc2 + k2) * N + n0 + 4*nq);
            cp16(base + (uint32_t)(2*A_STG + B_STG + k2*BPAD + 4*nq)*4, Wl + (size_t)(kc2 + k2) * N + n0 + 4*nq);
        }
    };

    auto compute = [&](int s) {
        const uint32_t* AsH = sm + (size_t)s * STG_W;
        const uint32_t* AsL = AsH + A_STG;
        const uint32_t* BsH = AsH + 2*A_STG;
        const uint32_t* BsL = BsH + B_STG;
        #pragma unroll
        for (int ks = 0; ks < 2; ks++) {
            const int k2 = ks * 8 + cq;
            uint32_t ah[4][4], al[4][4], bh[8][2], bl[8][2];
            #pragma unroll
            for (int mt = 0; mt < 4; mt++) {
                int row = wm*64 + mt*16 + r;
                ah[mt][0] = AsH[row*KP + k2];
                ah[mt][1] = AsH[(row+8)*KP + k2];
                ah[mt][2] = AsH[row*KP + k2 + 4];
                ah[mt][3] = AsH[(row+8)*KP + k2 + 4];
                al[mt][0] = AsL[row*KP + k2];
                al[mt][1] = AsL[(row+8)*KP + k2];
                al[mt][2] = AsL[row*KP + k2 + 4];
                al[mt][3] = AsL[(row+8)*KP + k2 + 4];
            }
            #pragma unroll
            for (int nt = 0; nt < 8; nt++) {
                int n = wn*64 + nt*8 + r;
                bh[nt][0] = BsH[k2*BPAD + n];
                bh[nt][1] = BsH[(k2+4)*BPAD + n];
                bl[nt][0] = BsL[k2*BPAD + n];
                bl[nt][1] = BsL[(k2+4)*BPAD + n];
            }
            #pragma unroll
            for (int mt = 0; mt < 4; mt++)
                #pragma unroll
                for (int nt = 0; nt < 8; nt++) {
                    mma_bf16(acc[mt][nt], ah[mt], bl[nt]);
                    mma_bf16(acc[mt][nt], al[mt], bh[nt]);
                    mma_bf16(acc[mt][nt], ah[mt], bh[nt]);
                }
        }
    };

    const int NC = K / BK;
    issue_loads(0, 0); CP_COMMIT();
    issue_loads(1, 1); CP_COMMIT();

    for (int c = 0; c < NC; c++) {
        CP_WAIT1();
        __syncthreads();
        if (c + 2 < NC) issue_loads(c + 2, (c + 2) % NSTAGE);
        CP_COMMIT();
        compute(c % NSTAGE);
    }

    const int cb = cq * 2;
    #pragma unroll
    for (int mt = 0; mt < 4; mt++) {
        #pragma unroll
        for (int nt = 0; nt < 8; nt++) {
            int m = m0 + wm*64 + mt*16 + r;
            int n = n0 + wn*64 + nt*8 + cb;
            float2 bv = *(const float2*)(bias + n);
            float2 v0, v1;
            v0.x = acc[mt][nt][0] + bv.x; v0.y = acc[mt][nt][1] + bv.y;
            v1.x = acc[mt][nt][2] + bv.x; v1.y = acc[mt][nt][3] + bv.y;
            if (HAS_RES) {
                float2 r0 = *(const float2*)(Res + (size_t)m * N + n);
                float2 r1 = *(const float2*)(Res + (size_t)(m + 8) * N + n);
                v0.x += r0.x; v0.y += r0.y; v1.x += r1.x; v1.y += r1.y;
            }
            *(float2*)(C + (size_t)m * N + n) = v0;
            *(float2*)(C + (size_t)(m + 8) * N + n) = v1;
        }
    }
}

// ================= fused flash attention =================
// grid: (T/128, B*H). 256 threads, 8 warps; warp owns 16 q-rows.
#define TQ 128
#define TK 128
#define QP 36
#define KB 132
#define VB 68
#define QH_OFF 0
#define QL_OFF 4608
#define KH_OFF 9216
#define KL_OFF (KH_OFF + 2*4224)
#define VH_OFF (KL_OFF + 2*4224)
#define VL_OFF (VH_OFF + 2*4352)
#define RB_OFF (VL_OFF + 2*4352)
#define ATT_SMEM_BYTES ((RB_OFF + 260)*4)

__global__ void __launch_bounds__(256, 1) attn_kernel(
    const uint32_t* __restrict__ qh, const uint32_t* __restrict__ ql,
    const uint32_t* __restrict__ kh, const uint32_t* __restrict__ kl,
    const uint32_t* __restrict__ vh, const uint32_t* __restrict__ vl,
    const float* __restrict__ relb,
    uint32_t* __restrict__ oh, uint32_t* __restrict__ ol)
{
    extern __shared__ uint32_t sm[];
    const uint32_t sb = smem_u32(sm);
    const int tid = threadIdx.x, lane = tid & 31, wid = tid >> 5;
    const int r = lane >> 2, cq = lane & 3;
    const int qt0 = blockIdx.x * TQ;
    const int bh = blockIdx.y;
    const int b = bh >> 4, h = bh & 15;

    float* rb_s = (float*)(sm + RB_OFF);
    for (int i = tid; i < 2*MREL + 1; i += 256) rb_s[i] = relb[i * H_ + h];   // FIXED: covers index 256

    const size_t qbase = ((size_t)bh * T_ + qt0) * 32;
    const size_t kbase = (size_t)bh * 32 * T_;
    const size_t vbase = (size_t)bh * 512 * 64;

    // load Q tile (persistent)
    {
        int t = tid >> 1, u = tid & 1;
        #pragma unroll
        for (int i = 0; i < 4; i++) {
            int un = u + 2*i;
            cp16(sb + (uint32_t)(QH_OFF + t*QP + un*4)*4, qh + qbase + (size_t)t*32 + un*4);
            cp16(sb + (uint32_t)(QL_OFF + t*QP + un*4)*4, ql + qbase + (size_t)t*32 + un*4);
        }
    }
    auto load_kv = [&](int kt, int s) {
        int kt0 = kt * TK;
        {
            int d2 = tid >> 3, j = tid & 7;
            #pragma unroll
            for (int i = 0; i < 4; i++) {
                int un = j + 8*i;
                cp16(sb + (uint32_t)(KH_OFF + s*4224 + d2*KB + un*4)*4, kh + kbase + (size_t)d2*T_ + kt0 + un*4);
                cp16(sb + (uint32_t)(KL_OFF + s*4224 + d2*KB + un*4)*4, kl + kbase + (size_t)d2*T_ + kt0 + un*4);
            }
        }
        {
            int t2 = tid >> 2, u = tid & 3;
            #pragma unroll
            for (int i = 0; i < 4; i++) {
                int un = u + 4*i;
                cp16(sb + (uint32_t)(VH_OFF + s*4352 + t2*VB + un*4)*4, vh + vbase + (size_t)(kt0/2 + t2)*64 + un*4);
                cp16(sb + (uint32_t)(VL_OFF + s*4352 + t2*VB + un*4)*4, vl + vbase + (size_t)(kt0/2 + t2)*64 + un*4);
            }
        }
    };

    load_kv(0, 0);
    CP_COMMIT();
    CP_WAIT0();
    __syncthreads();

    const int wq = wid * 16;
    const int qi0 = qt0 + wq + r, qi1 = qi0 + 8;
    float m0 = -1e30f, m1 = -1e30f, l0 = 0.f, l1 = 0.f;
    float oacc[8][4];
    #pragma unroll
    for (int i = 0; i < 8; i++)
        #pragma unroll
        for (int q = 0; q < 4; q++) oacc[i][q] = 0.f;

    const int NKT = T_ / TK;
    for (int kt = 0; kt < NKT; kt++) {
        const int s = kt & 1;
        if (kt + 1 < NKT) load_kv(kt + 1, (kt + 1) & 1);
        CP_COMMIT();

        const uint32_t* QsH = sm + QH_OFF;
        const uint32_t* QsL = sm + QL_OFF;
        const uint32_t* KsH = sm + KH_OFF + s*4224;
        const uint32_t* KsL = sm + KL_OFF + s*4224;
        const uint32_t* VsH = sm + VH_OFF + s*4352;
        const uint32_t* VsL = sm + VL_OFF + s*4352;

        // ---- scores ----
        float sacc[16][4];
        #pragma unroll
        for (int nt = 0; nt < 16; nt++)
            #pragma unroll
            for (int q = 0; q < 4; q++) sacc[nt][q] = 0.f;

        #pragma unroll
        for (int ks = 0; ks < 4; ks++) {
            const int k2 = ks * 8 + cq;
            uint32_t a_h[4], a_l[4];
            a_h[0] = QsH[(wq+r)*QP + k2];   a_h[1] = QsH[(wq+8+r)*QP + k2];
            a_h[2] = QsH[(wq+r)*QP + k2+4]; a_h[3] = QsH[(wq+8+r)*QP + k2+4];
            a_l[0] = QsL[(wq+r)*QP + k2];   a_l[1] = QsL[(wq+8+r)*QP + k2];
            a_l[2] = QsL[(wq+r)*QP + k2+4]; a_l[3] = QsL[(wq+8+r)*QP + k2+4];
            #pragma unroll
            for (int nt = 0; nt < 16; nt++) {
                uint32_t b_h[2], b_l[2];
                b_h[0] = KsH[k2*KB + nt*8 + r];
                b_h[1] = KsH[(k2+4)*KB + nt*8 + r];
                b_l[0] = KsL[k2*KB + nt*8 + r];
                b_l[1] = KsL[(k2+4)*KB + nt*8 + r];
                mma_bf16(sacc[nt], a_h, b_l);
                mma_bf16(sacc[nt], a_l, b_h);
                mma_bf16(sacc[nt], a_h, b_h);
            }
        }

        // ---- bias + online softmax ----
        float tm0 = -1e30f, tm1 = -1e30f;
        #pragma unroll
        for (int nt = 0; nt < 16; nt++) {
            int kj = kt*TK + nt*8 + 2*cq;
            int i00 = min(max(kj   - qi0, -MREL), MREL) + MREL;
            int i01 = min(max(kj+1 - qi0, -MREL), MREL) + MREL;
            int i10 = min(max(kj   - qi1, -MREL), MREL) + MREL;
            int i11 = min(max(kj+1 - qi1, -MREL), MREL) + MREL;
            sacc[nt][0] += rb_s[i00];
            sacc[nt][1] += rb_s[i01];
            sacc[nt][2] += rb_s[i10];
            sacc[nt][3] += rb_s[i11];
            tm0 = fmaxf(tm0, fmaxf(sacc[nt][0], sacc[nt][1]));
            tm1 = fmaxf(tm1, fmaxf(sacc[nt][2], sacc[nt][3]));
        }
        tm0 = qmax(tm0); tm1 = qmax(tm1);
        float nm0 = fmaxf(m0, tm0), nm1 = fmaxf(m1, tm1);
        float sc0 = __expf(m0 - nm0), sc1 = __expf(m1 - nm1);
        l0 *= sc0; l1 *= sc1;
        #pragma unroll
        for (int i = 0; i < 8; i++) {
            oacc[i][0] *= sc0; oacc[i][1] *= sc0;
            oacc[i][2] *= sc1; oacc[i][3] *= sc1;
        }
        float rs0 = 0.f, rs1 = 0.f;
        #pragma unroll
        for (int nt = 0; nt < 16; nt++) {
            float p0 = __expf(sacc[nt][0] - nm0);
            float p1 = __expf(sacc[nt][1] - nm0);
            float p2 = __expf(sacc[nt][2] - nm1);
            float p3 = __expf(sacc[nt][3] - nm1);
            sacc[nt][0] = p0; sacc[nt][1] = p1; sacc[nt][2] = p2; sacc[nt][3] = p3;
            rs0 += p0 + p1; rs1 += p2 + p3;
        }
        l0 += qsum(rs0); l1 += qsum(rs1);
        m0 = nm0; m1 = nm1;

        // ---- P @ V ----
        #pragma unroll
        for (int kk = 0; kk < 8; kk++) {
            uint32_t p_h[4], p_l[4];
            float ra, rb;
            p_h[0] = pack_hi(sacc[2*kk][0],   sacc[2*kk][1],   ra, rb); p_l[0] = pack_lo(ra, rb);
            p_h[1] = pack_hi(sacc[2*kk][2],   sacc[2*kk][3],   ra, rb); p_l[1] = pack_lo(ra, rb);
            p_h[2] = pack_hi(sacc[2*kk+1][0], sacc[2*kk+1][1], ra, rb); p_l[2] = pack_lo(ra, rb);
            p_h[3] = pack_hi(sacc[2*kk+1][2], sacc[2*kk+1][3], ra, rb); p_l[3] = pack_lo(ra, rb);
            const int t2 = kk * 8 + cq;
            #pragma unroll
            for (int ntd = 0; ntd < 8; ntd++) {
                uint32_t b_h[2], b_l[2];
                b_h[0] = VsH[t2*VB + ntd*8 + r];
                b_h[1] = VsH[(t2+4)*VB + ntd*8 + r];
                b_l[0] = VsL[t2*VB + ntd*8 + r];
                b_l[1] = VsL[(t2+4)*VB + ntd*8 + r];
                mma_bf16(oacc[ntd], p_h, b_l);
                mma_bf16(oacc[ntd], p_l, b_h);
                mma_bf16(oacc[ntd], p_h, b_h);
            }
        }

        CP_WAIT0();
        __syncthreads();
    }

    // ---- finalize + packed store (feeds proj GEMM) ----
    float inv0 = 1.f / l0, inv1 = 1.f / l1;
    const size_t ob0 = ((size_t)(b*T_ + qt0 + wq + r))*512 + h*32;
    const size_t ob1 = ((size_t)(b*T_ + qt0 + wq + r + 8))*512 + h*32;
    #pragma unroll
    for (int ntd = 0; ntd < 8; ntd++) {
        int d2 = ntd*4 + cq;
        float ra, rb;
        uint32_t w0 = pack_hi(oacc[ntd][0]*inv0, oacc[ntd][1]*inv0, ra, rb);
        uint32_t w0l = pack_lo(ra, rb);
        uint32_t w1 = pack_hi(oacc[ntd][2]*inv1, oacc[ntd][3]*inv1, ra, rb);
        uint32_t w1l = pack_lo(ra, rb);
        oh[ob0 + d2] = w0; ol[ob0 + d2] = w0l;
        oh[ob1 + d2] = w1; ol[ob1 + d2] = w1l;
    }
}

// ---------------- block reduction ----------------
__device__ __forceinline__ float block_reduce_sum(float v) {
    __shared__ float sh[33];
    int lane = threadIdx.x & 31, wid = threadIdx.x >> 5;
    #pragma unroll
    for (int o = 16; o > 0; o >>= 1) v += __shfl_xor_sync(0xffffffffu, v, o);
    if (lane == 0) sh[wid] = v;
    __syncthreads();
    if (wid == 0) {
        float t = (lane < 8) ? sh[lane] : 0.f;
        #pragma unroll
        for (int o = 4; o > 0; o >>= 1) t += __shfl_xor_sync(0xffffffffu, t, o);
        if (lane == 0) sh[32] = t;
    }
    __syncthreads();
    return sh[32];
}

// ---------------- LayerNorm fp32 out (for ln_in only) ----------------
__global__ void __launch_bounds__(256) ln_kernel(
    const float* __restrict__ x, const float* __restrict__ g,
    const float* __restrict__ b, float* __restrict__ y)
{
    int row = blockIdx.x;
    const float* xr = x + (size_t)row * D_;
    float v[4];
    float s = 0.f;
    #pragma unroll
    for (int j = 0; j < 4; j++) { v[j] = xr[threadIdx.x + j * 256]; s += v[j]; }
    float mean = block_reduce_sum(s) * (1.0f / D_);
    float var = 0.f;
    #pragma unroll
    for (int j = 0; j < 4; j++) { float d0 = v[j] - mean; var += d0 * d0; }
    var = block_reduce_sum(var) * (1.0f / D_);
    float rstd = rsqrtf(var + 1e-5f);
    float* yr = y + (size_t)row * D_;
    #pragma unroll
    for (int j = 0; j < 4; j++) {
        int c = threadIdx.x + j * 256;
        yr[c] = (v[j] - mean) * rstd * g[c] + b[c];
    }
}

// ---------------- LayerNorm -> packed hi/lo (feeds GEMMs) ----------------
__global__ void __launch_bounds__(256) ln_pack_kernel(
    const float* __restrict__ x, const float* __restrict__ g,
    const float* __restrict__ b, uint32_t* __restrict__ ah, uint32_t* __restrict__ al)
{
    int row = blockIdx.x;
    const float* xr = x + (size_t)row * D_;
    float4 v = *(const float4*)(xr + threadIdx.x * 4);
    float s = v.x + v.y + v.z + v.w;
    float mean = block_reduce_sum(s) * (1.0f / D_);
    float dx = v.x - mean, dy = v.y - mean, dz = v.z - mean, dw = v.w - mean;
    float var = dx*dx + dy*dy + dz*dz + dw*dw;
    var = block_reduce_sum(var) * (1.0f / D_);
    float rstd = rsqrtf(var + 1e-5f);
    int c = threadIdx.x * 4;
    float4 gg = *(const float4*)(g + c);
    float4 bb = *(const float4*)(b + c);
    float y0 = dx * rstd * gg.x + bb.x;
    float y1 = dy * rstd * gg.y + bb.y;
    float y2 = dz * rstd * gg.z + bb.z;
    float y3 = dw * rstd * gg.w + bb.w;
    float ra, rb;
    size_t base = (size_t)row * 512 + threadIdx.x * 2;
    ah[base]   = pack_hi(y0, y1, ra, rb); al[base]   = pack_lo(ra, rb);
    ah[base+1] = pack_hi(y2, y3, ra, rb); al[base+1] = pack_lo(ra, rb);
}

// ---------------- GeGLU -> packed hi/lo ----------------
__global__ void __launch_bounds__(256) geglu_pack_kernel(
    const float* __restrict__ ff1, uint32_t* __restrict__ ah, uint32_t* __restrict__ al)
{
    int idx = blockIdx.x * 256 + threadIdx.x;   // BT * 2048
    int m = idx >> 11, f2 = idx & 2047;
    float2 a = *(const float2*)(ff1 + (size_t)m * (2*FF_) + 2*f2);
    float2 g = *(const float2*)(ff1 + (size_t)m * (2*FF_) + FF_ + 2*f2);
    float ge0 = 0.5f * g.x * (1.0f + erff(g.x * 0.70710678118654752f));
    float ge1 = 0.5f * g.y * (1.0f + erff(g.y * 0.70710678118654752f));
    float v0 = a.x * ge0, v1 = a.y * ge1;
    float ra, rb;
    ah[idx] = pack_hi(v0, v1, ra, rb);
    al[idx] = pack_lo(ra, rb);
}

// ---------------- final scaling epilogue ----------------
__global__ void __launch_bounds__(256) final_kernel(
    const float* __restrict__ o, const float* __restrict__ alpha,
    const float* __restrict__ beta, const float* __restrict__ alpha_scale,
    const float* __restrict__ beta_scale, float* __restrict__ out)
{
    int row = blockIdx.x;
    const float* orow = o + (size_t)row * D_;
    float v[4];
    float ss = 0.f;
    #pragma unroll
    for (int j = 0; j < 4; j++) { v[j] = orow[threadIdx.x + j * 256]; ss += v[j] * v[j]; }
    ss = block_reduce_sum(ss);
    float ms = sqrtf(ss);
    float a_s = fminf(fmaxf(alpha_scale[0], 0.f), 1.f);
    float sc = 1.0f + alpha[0] * a_s * fminf(ms, 5.0f);
    float bb = beta[0] * beta_scale[0];
    #pragma unroll
    for (int j = 0; j < 4; j++) {
        int c = threadIdx.x + j * 256;
        float val = v[j] * sc + bb;
        val = fminf(fmaxf(val, -10.0f), 10.0f);
        out[(size_t)row * D_ + c] = val + v[j];
    }
}

// ---------------- launch ----------------
extern "C" void kernel_launch(void* const* d_in, const int* in_sizes, int n_in,
                              void* d_out, int out_size)
{
    const float* x           = (const float*)d_in[0];
    const float* context     = (const float*)d_in[1];
    const float* W_in        = (const float*)d_in[2];
    const float* b_in        = (const float*)d_in[3];
    const float* ln_in_g     = (const float*)d_in[4];
    const float* ln_in_b     = (const float*)d_in[5];
    const float* ln1_g       = (const float*)d_in[6];
    const float* ln1_b       = (const float*)d_in[7];
    const float* Wqkv        = (const float*)d_in[8];
    const float* bqkv        = (const float*)d_in[9];
    const float* Wproj       = (const float*)d_in[10];
    const float* bproj       = (const float*)d_in[11];
    const float* rel_bias    = (const float*)d_in[12];
    const float* ln2_g       = (const float*)d_in[13];
    const float* ln2_b       = (const float*)d_in[14];
    const float* Wfc1        = (const float*)d_in[15];
    const float* bfc1        = (const float*)d_in[16];
    const float* Wfc2        = (const float*)d_in[17];
    const float* bfc2        = (const float*)d_in[18];
    const float* ln_f_g      = (const float*)d_in[19];
    const float* ln_f_b      = (const float*)d_in[20];
    const float* W_out       = (const float*)d_in[21];
    const float* b_out       = (const float*)d_in[22];
    const float* alpha       = (const float*)d_in[23];
    const float* beta        = (const float*)d_in[24];
    const float* alpha_scale = (const float*)d_in[25];
    const float* beta_scale  = (const float*)d_in[26];
    float* out = (float*)d_out;

    float *h, *tmp, *qkv, *ff1;
    uint32_t *ah, *al, *wh, *wl, *qh, *ql, *kh, *kl, *vh, *vl;
    cudaGetSymbolAddress((void**)&h,   g_h);
    cudaGetSymbolAddress((void**)&tmp, g_tmp);
    cudaGetSymbolAddress((void**)&qkv, g_qkv);
    cudaGetSymbolAddress((void**)&ff1, g_ff1);
    cudaGetSymbolAddress((void**)&ah,  g_ah);
    cudaGetSymbolAddress((void**)&al,  g_al);
    cudaGetSymbolAddress((void**)&wh,  g_wh);
    cudaGetSymbolAddress((void**)&wl,  g_wl);
    cudaGetSymbolAddress((void**)&qh,  g_qh);
    cudaGetSymbolAddress((void**)&ql,  g_ql);
    cudaGetSymbolAddress((void**)&kh,  g_kh);
    cudaGetSymbolAddress((void**)&kl,  g_kl);
    cudaGetSymbolAddress((void**)&vh,  g_vh);
    cudaGetSymbolAddress((void**)&vl,  g_vl);

    cudaFuncSetAttribute(gemm_bf16x3<true>,  cudaFuncAttributeMaxDynamicSharedMemorySize, G_SMEM_BYTES);
    cudaFuncSetAttribute(gemm_bf16x3<false>, cudaFuncAttributeMaxDynamicSharedMemorySize, G_SMEM_BYTES);
    cudaFuncSetAttribute(attn_kernel, cudaFuncAttributeMaxDynamicSharedMemorySize, ATT_SMEM_BYTES);

    // ---- weight pre-conversion ----
    convw_kernel<<<dim3((int)(WSZ_IN/256), 1),   256>>>(W_in,  wh + WOFF_IN,   wl + WOFF_IN,   D_,  D_);
    convw_kernel<<<dim3((int)(WSZ_QKV/256), L_), 256>>>(Wqkv,  wh + WOFF_QKV,  wl + WOFF_QKV,  D_,  3*D_);
    convw_kernel<<<dim3((int)(WSZ_PROJ/256), L_),256>>>(Wproj, wh + WOFF_PROJ, wl + WOFF_PROJ, D_,  D_);
    convw_kernel<<<dim3((int)(WSZ_FC1/256), L_), 256>>>(Wfc1,  wh + WOFF_FC1,  wl + WOFF_FC1,  D_,  2*FF_);
    convw_kernel<<<dim3((int)(WSZ_FC2/256), L_), 256>>>(Wfc2,  wh + WOFF_FC2,  wl + WOFF_FC2,  FF_, D_);
    convw_kernel<<<dim3((int)(WSZ_IN/256), 1),   256>>>(W_out, wh + WOFF_OUT,  wl + WOFF_OUT,  D_,  D_);

    #define GEMM(RES, N, K, WOFF, bias, res, dst) \
        gemm_bf16x3<RES><<<dim3((N)/BN, BT_/BM), 256, G_SMEM_BYTES>>>( \
            ah, al, wh + (WOFF), wl + (WOFF), (bias), (res), (dst), BT_, (N), (K))

    // pre: h = LN(x @ W_in + b_in + context)
    conva_kernel<<<(BT_*D_/2)/256, 256>>>(x, ah, al, D_/2);
    GEMM(true, D_, D_, WOFF_IN, b_in, context, tmp);
    ln_kernel<<<BT_, 256>>>(tmp, ln_in_g, ln_in_b, h);

    for (int l = 0; l < L_; l++) {
        // attention block
        ln_pack_kernel<<<BT_, 256>>>(h, ln1_g + l*D_, ln1_b + l*D_, ah, al);
        GEMM(false, 3*D_, D_, WOFF_QKV + (size_t)l*WSZ_QKV, bqkv + l*3*D_, nullptr, qkv);
        ropeconv_kernel<<<(B_*H_*T_*32)/256, 256>>>(qkv, qh, ql, kh, kl, vh, vl);
        attn_kernel<<<dim3(T_/TQ, B_*H_), 256, ATT_SMEM_BYTES>>>(
            qh, ql, kh, kl, vh, vl, rel_bias + (size_t)l*(2*MREL+1)*H_, ah, al);
        GEMM(true, D_, D_, WOFF_PROJ + (size_t)l*WSZ_PROJ, bproj + l*D_, h, h);

        // FFN block
        ln_pack_kernel<<<BT_, 256>>>(h, ln2_g + l*D_, ln2_b + l*D_, ah, al);
        GEMM(false, 2*FF_, D_, WOFF_FC1 + (size_t)l*WSZ_FC1, bfc1 + l*2*FF_, nullptr, ff1);
        geglu_pack_kernel<<<(BT_*FF_/2)/256, 256>>>(ff1, ah, al);
        GEMM(true, D_, FF_, WOFF_FC2 + (size_t)l*WSZ_FC2, bfc2 + l*D_, h, h);
    }

    // post
    ln_pack_kernel<<<BT_, 256>>>(h, ln_f_g, ln_f_b, ah, al);
    GEMM(false, D_, D_, WOFF_OUT, b_out, nullptr, tmp);
    final_kernel<<<BT_, 256>>>(tmp, alpha, beta, alpha_scale, beta_scale, out);
}

// round 10
// speedup vs baseline: 2.6038x; 1.1761x over previous
#include <cuda_runtime.h>
#include <cuda_bf16.h>
#include <math.h>
#include <stdint.h>

#define B_  2
#define T_  1024
#define D_  1024
#define H_  16
#define HD_ 64
#define FF_ 4096
#define L_  4
#define MREL 128
#define BT_ (B_*T_)   // 2048

// ---------------- scratch (no allocs allowed) ----------------
__device__ float g_h[BT_*D_];          // 8 MB
__device__ float g_tmp[BT_*D_];        // 8 MB
__device__ float g_qkv[BT_*3*D_];      // 24 MB
__device__ float g_ff1[BT_*2*FF_];     // 64 MB

// bf16x2-packed activations (hi/lo), max M*K = 2048*4096
__device__ uint32_t g_ah[(size_t)BT_*FF_/2];
__device__ uint32_t g_al[(size_t)BT_*FF_/2];

// attention operands, bf16x2 words
__device__ uint32_t g_qh[(size_t)B_*H_*T_*32];  // [bh][t][d2]
__device__ uint32_t g_ql[(size_t)B_*H_*T_*32];
__device__ uint32_t g_kh[(size_t)B_*H_*32*T_];  // [bh][d2][t]
__device__ uint32_t g_kl[(size_t)B_*H_*32*T_];
__device__ uint32_t g_vh[(size_t)B_*H_*512*64]; // [bh][t2][d]
__device__ uint32_t g_vl[(size_t)B_*H_*512*64];

// bf16x2-packed weights (hi/lo), word layout [K/2][N]
#define WOFF_IN   ((size_t)0)
#define WSZ_IN    ((size_t)D_*D_/2)
#define WOFF_QKV  (WOFF_IN + WSZ_IN)
#define WSZ_QKV   ((size_t)D_*3*D_/2)
#define WOFF_PROJ (WOFF_QKV + L_*WSZ_QKV)
#define WSZ_PROJ  ((size_t)D_*D_/2)
#define WOFF_FC1  (WOFF_PROJ + L_*WSZ_PROJ)
#define WSZ_FC1   ((size_t)D_*2*FF_/2)
#define WOFF_FC2  (WOFF_FC1 + L_*WSZ_FC1)
#define WSZ_FC2   ((size_t)FF_*D_/2)
#define WOFF_OUT  (WOFF_FC2 + L_*WSZ_FC2)
#define WTOT      (WOFF_OUT + (size_t)D_*D_/2)
__device__ uint32_t g_wh[WTOT];
__device__ uint32_t g_wl[WTOT];

// ---------------- helpers ----------------
__device__ __forceinline__ uint32_t smem_u32(const void* p) {
    uint32_t a;
    asm("{ .reg .u64 t; cvta.to.shared.u64 t, %1; cvt.u32.u64 %0, t; }" : "=r"(a) : "l"(p));
    return a;
}
__device__ __forceinline__ uint32_t pack_hi(float a, float b, float& ra, float& rb) {
    __nv_bfloat16 ba = __float2bfloat16_rn(a), bb = __float2bfloat16_rn(b);
    ra = a - __bfloat162float(ba);
    rb = b - __bfloat162float(bb);
    uint16_t ua = *(uint16_t*)&ba, ub = *(uint16_t*)&bb;
    return (uint32_t)ua | ((uint32_t)ub << 16);
}
__device__ __forceinline__ uint32_t pack_lo(float ra, float rb) {
    __nv_bfloat16 ba = __float2bfloat16_rn(ra), bb = __float2bfloat16_rn(rb);
    uint16_t ua = *(uint16_t*)&ba, ub = *(uint16_t*)&bb;
    return (uint32_t)ua | ((uint32_t)ub << 16);
}
__device__ __forceinline__ void cp16(uint32_t dst, const void* src) {
    asm volatile("cp.async.cg.shared.global [%0], [%1], 16;" :: "r"(dst), "l"(src));
}
#define CP_COMMIT() asm volatile("cp.async.commit_group;" ::: "memory")
#define CP_WAIT1()  asm volatile("cp.async.wait_group 1;" ::: "memory")
#define CP_WAIT0()  asm volatile("cp.async.wait_group 0;" ::: "memory")

__device__ __forceinline__ void mma_bf16(float c[4], const uint32_t a[4], const uint32_t b[2]) {
    asm volatile(
        "mma.sync.aligned.m16n8k16.row.col.f32.bf16.bf16.f32 "
        "{%0,%1,%2,%3}, {%4,%5,%6,%7}, {%8,%9}, {%0,%1,%2,%3};"
        : "+f"(c[0]), "+f"(c[1]), "+f"(c[2]), "+f"(c[3])
        : "r"(a[0]), "r"(a[1]), "r"(a[2]), "r"(a[3]), "r"(b[0]), "r"(b[1]));
}
__device__ __forceinline__ float qmax(float v) {
    v = fmaxf(v, __shfl_xor_sync(0xffffffffu, v, 1));
    v = fmaxf(v, __shfl_xor_sync(0xffffffffu, v, 2));
    return v;
}
__device__ __forceinline__ float qsum(float v) {
    v += __shfl_xor_sync(0xffffffffu, v, 1);
    v += __shfl_xor_sync(0xffffffffu, v, 2);
    return v;
}

// ---------------- conversion kernels ----------------
__global__ void __launch_bounds__(256) convw_kernel(
    const float* __restrict__ W, uint32_t* __restrict__ hi, uint32_t* __restrict__ lo,
    int K, int N)
{
    size_t slice = (size_t)blockIdx.y;
    const float* Wp = W + slice * K * N;
    uint32_t* hp = hi + slice * (K/2) * N;
    uint32_t* lp = lo + slice * (K/2) * N;
    int w = blockIdx.x * 256 + threadIdx.x;
    int n = w % N, k2 = w / N;
    float a = Wp[(size_t)(2*k2) * N + n];
    float b = Wp[(size_t)(2*k2+1) * N + n];
    float ra, rb;
    hp[w] = pack_hi(a, b, ra, rb);
    lp[w] = pack_lo(ra, rb);
}

__global__ void __launch_bounds__(256) conva_kernel(
    const float* __restrict__ A, uint32_t* __restrict__ hi, uint32_t* __restrict__ lo,
    int K2)
{
    int w = blockIdx.x * 256 + threadIdx.x;
    int k2 = w % K2, m = w / K2;
    float2 v = *(const float2*)(A + (size_t)m * (2*K2) + 2*k2);
    float ra, rb;
    hi[w] = pack_hi(v.x, v.y, ra, rb);
    lo[w] = pack_lo(ra, rb);
}

// rope + pack qkv into attention layouts; idx space = B*H*T*32 = 1M
__global__ void __launch_bounds__(256) ropeconv_kernel(
    const float* __restrict__ qkv,
    uint32_t* __restrict__ qh, uint32_t* __restrict__ ql,
    uint32_t* __restrict__ kh, uint32_t* __restrict__ kl,
    uint32_t* __restrict__ vh, uint32_t* __restrict__ vl)
{
    int idx = blockIdx.x * 256 + threadIdx.x;
    float ra, rb;
    const float LN1E4 = 9.210340371976184f;   // ln(10000)
    // Q: (b, h, t, p), p inner
    {
        int p = idx & 31, t = (idx >> 5) & 1023, hh = (idx >> 15) & 15, b = idx >> 19;
        size_t src = ((size_t)(b*T_ + t)*3 + 0)*D_ + hh*64 + 2*p;
        float x1 = qkv[src], x2 = qkv[src+1];
        float theta = (float)t * __expf(-(float)(2*((2*p) & 31)) * (1.f/64.f) * LN1E4);
        float sn, cs; sincosf(theta, &sn, &cs);
        float e = (x1*cs - x2*sn) * 0.125f;
        float o = (x1*sn + x2*cs) * 0.125f;
        size_t dst = ((size_t)(b*16 + hh)*T_ + t)*32 + p;
        qh[dst] = pack_hi(e, o, ra, rb); ql[dst] = pack_lo(ra, rb);
    }
    // K: (b, h, p, t), t inner -> transposed [d2][t]
    {
        int t = idx & 1023, p = (idx >> 10) & 31, hh = (idx >> 15) & 15, b = idx >> 19;
        size_t src = ((size_t)(b*T_ + t)*3 + 1)*D_ + hh*64 + 2*p;
        float x1 = qkv[src], x2 = qkv[src+1];
        float theta = (float)t * __expf(-(float)(2*((2*p) & 31)) * (1.f/64.f) * LN1E4);
        float sn, cs; sincosf(theta, &sn, &cs);
        float e = x1*cs - x2*sn;
        float o = x1*sn + x2*cs;
        size_t dst = ((size_t)(b*16 + hh)*32 + p)*T_ + t;
        kh[dst] = pack_hi(e, o, ra, rb); kl[dst] = pack_lo(ra, rb);
    }
    // V: (b, h, t2, d), d inner -> [t2][d] pairs across t
    {
        int d = idx & 63, t2 = (idx >> 6) & 511, hh = (idx >> 15) & 15, b = idx >> 19;
        size_t s0 = ((size_t)(b*T_ + 2*t2)*3 + 2)*D_ + hh*64 + d;
        float v0 = qkv[s0], v1 = qkv[s0 + 3*D_];
        size_t dst = ((size_t)(b*16 + hh)*512 + t2)*64 + d;
        vh[dst] = pack_hi(v0, v1, ra, rb); vl[dst] = pack_lo(ra, rb);
    }
}

// ================= bf16x3 mma.sync GEMM (templated on BN) =================
// C[M,N] = A[M,K] @ W[K,N] + bias (+ Res).  Operands pre-packed bf16x2 hi/lo.
// CTA 128 x BNv, 8 warps (2x4), warp tile 64x(BNv/4), BK=32, 3-stage cp.async.
#define BM 128
#define BK 32
#define KP 20
#define A_STG (BM*KP)
#define NSTAGE 3
constexpr int smb(int BNv) { return NSTAGE * (2*A_STG + 2*16*(BNv + 8)) * 4; }

template<bool HAS_RES, int BNv>
__global__ void __launch_bounds__(256, 1) gemm_bf16x3(
    const uint32_t* __restrict__ Ah, const uint32_t* __restrict__ Al,
    const uint32_t* __restrict__ Wh, const uint32_t* __restrict__ Wl,
    const float* __restrict__ bias, const float* __restrict__ Res,
    float* __restrict__ C, int M, int N, int K)
{
    constexpr int NT    = BNv / 32;           // n-tiles per warp
    constexpr int BPADv = BNv + 8;
    constexpr int B_STGv = 16 * BPADv;
    constexpr int STG_Wv = 2*A_STG + 2*B_STGv;
    constexpr int TPR   = BNv / 4;            // threads per B k2-row
    constexpr int RPP   = 256 / TPR;          // rows per pass
    constexpr int NJ    = 16 / RPP;           // passes

    extern __shared__ uint32_t sm[];
    const uint32_t smem_base = smem_u32(sm);

    const int tid = threadIdx.x;
    const int lane = tid & 31, wid = tid >> 5;
    const int wm = wid >> 2, wn = wid & 3;
    const int m0 = blockIdx.y * BM, n0 = blockIdx.x * BNv;
    const int r = lane >> 2, cq = lane & 3;
    const int K2 = K >> 1;

    float acc[4][NT][4];
    #pragma unroll
    for (int i = 0; i < 4; i++)
        #pragma unroll
        for (int j = 0; j < NT; j++)
            #pragma unroll
            for (int q = 0; q < 4; q++) acc[i][j][q] = 0.f;

    const int am = tid & 127, aqh = tid >> 7;
    const int nq = tid % TPR, k2b = tid / TPR;

    auto issue_loads = [&](int c, int s) {
        const int kc2 = c * 16;
        const uint32_t base = smem_base + (uint32_t)s * STG_Wv * 4;
        #pragma unroll
        for (int j = 0; j < 2; j++) {
            int q = aqh * 2 + j;
            cp16(base + (uint32_t)(am*KP + 4*q)*4, Ah + (size_t)(m0 + am) * K2 + kc2 + 4*q);
            cp16(base + (uint32_t)(A_STG + am*KP + 4*q)*4, Al + (size_t)(m0 + am) * K2 + kc2 + 4*q);
        }
        #pragma unroll
        for (int j = 0; j < NJ; j++) {
            int k2 = k2b + RPP*j;
            cp16(base + (uint32_t)(2*A_STG + k2*BPADv + 4*nq)*4, Wh + (size_t)(kc2 + k2) * N + n0 + 4*nq);
            cp16(base + (uint32_t)(2*A_STG + B_STGv + k2*BPADv + 4*nq)*4, Wl + (size_t)(kc2 + k2) * N + n0 + 4*nq);
        }
    };

    auto compute = [&](int s) {
        const uint32_t* AsH = sm + (size_t)s * STG_Wv;
        const uint32_t* AsL = AsH + A_STG;
        const uint32_t* BsH = AsH + 2*A_STG;
        const uint32_t* BsL = BsH + B_STGv;
        #pragma unroll
        for (int ks = 0; ks < 2; ks++) {
            const int k2 = ks * 8 + cq;
            uint32_t ah[4][4], al[4][4], bh[NT][2], bl[NT][2];
            #pragma unroll
            for (int mt = 0; mt < 4; mt++) {
                int row = wm*64 + mt*16 + r;
                ah[mt][0] = AsH[row*KP + k2];
                ah[mt][1] = AsH[(row+8)*KP + k2];
                ah[mt][2] = AsH[row*KP + k2 + 4];
                ah[mt][3] = AsH[(row+8)*KP + k2 + 4];
                al[mt][0] = AsL[row*KP + k2];
                al[mt][1] = AsL[(row+8)*KP + k2];
                al[mt][2] = AsL[row*KP + k2 + 4];
                al[mt][3] = AsL[(row+8)*KP + k2 + 4];
            }
            #pragma unroll
            for (int nt = 0; nt < NT; nt++) {
                int n = wn*(BNv/4) + nt*8 + r;
                bh[nt][0] = BsH[k2*BPADv + n];
                bh[nt][1] = BsH[(k2+4)*BPADv + n];
                bl[nt][0] = BsL[k2*BPADv + n];
                bl[nt][1] = BsL[(k2+4)*BPADv + n];
            }
            #pragma unroll
            for (int mt = 0; mt < 4; mt++)
                #pragma unroll
                for (int nt = 0; nt < NT; nt++) {
                    mma_bf16(acc[mt][nt], ah[mt], bl[nt]);
                    mma_bf16(acc[mt][nt], al[mt], bh[nt]);
                    mma_bf16(acc[mt][nt], ah[mt], bh[nt]);
                }
        }
    };

    const int NC = K / BK;
    issue_loads(0, 0); CP_COMMIT();
    issue_loads(1, 1); CP_COMMIT();

    for (int c = 0; c < NC; c++) {
        CP_WAIT1();
        __syncthreads();
        if (c + 2 < NC) issue_loads(c + 2, (c + 2) % NSTAGE);
        CP_COMMIT();
        compute(c % NSTAGE);
    }

    const int cb = cq * 2;
    #pragma unroll
    for (int mt = 0; mt < 4; mt++) {
        #pragma unroll
        for (int nt = 0; nt < NT; nt++) {
            int m = m0 + wm*64 + mt*16 + r;
            int n = n0 + wn*(BNv/4) + nt*8 + cb;
            float2 bv = *(const float2*)(bias + n);
            float2 v0, v1;
            v0.x = acc[mt][nt][0] + bv.x; v0.y = acc[mt][nt][1] + bv.y;
            v1.x = acc[mt][nt][2] + bv.x; v1.y = acc[mt][nt][3] + bv.y;
            if (HAS_RES) {
                float2 r0 = *(const float2*)(Res + (size_t)m * N + n);
                float2 r1 = *(const float2*)(Res + (size_t)(m + 8) * N + n);
                v0.x += r0.x; v0.y += r0.y; v1.x += r1.x; v1.y += r1.y;
            }
            *(float2*)(C + (size_t)m * N + n) = v0;
            *(float2*)(C + (size_t)(m + 8) * N + n) = v1;
        }
    }
}

// ================= fused flash attention =================
// grid: (T/128, B*H). 256 threads, 8 warps; warp owns 16 q-rows.
#define TQ 128
#define TK 128
#define QP 36
#define KB 132
#define VB 68
#define QH_OFF 0
#define QL_OFF 4608
#define KH_OFF 9216
#define KL_OFF (KH_OFF + 2*4224)
#define VH_OFF (KL_OFF + 2*4224)
#define VL_OFF (VH_OFF + 2*4352)
#define RB_OFF (VL_OFF + 2*4352)
#define ATT_SMEM_BYTES ((RB_OFF + 260)*4)

__global__ void __launch_bounds__(256, 1) attn_kernel(
    const uint32_t* __restrict__ qh, const uint32_t* __restrict__ ql,
    const uint32_t* __restrict__ kh, const uint32_t* __restrict__ kl,
    const uint32_t* __restrict__ vh, const uint32_t* __restrict__ vl,
    const float* __restrict__ relb,
    uint32_t* __restrict__ oh, uint32_t* __restrict__ ol)
{
    extern __shared__ uint32_t sm[];
    const uint32_t sb = smem_u32(sm);
    const int tid = threadIdx.x, lane = tid & 31, wid = tid >> 5;
    const int r = lane >> 2, cq = lane & 3;
    const int qt0 = blockIdx.x * TQ;
    const int bh = blockIdx.y;
    const int b = bh >> 4, h = bh & 15;

    float* rb_s = (float*)(sm + RB_OFF);
    for (int i = tid; i < 2*MREL + 1; i += 256) rb_s[i] = relb[i * H_ + h];

    const size_t qbase = ((size_t)bh * T_ + qt0) * 32;
    const size_t kbase = (size_t)bh * 32 * T_;
    const size_t vbase = (size_t)bh * 512 * 64;

    // load Q tile (persistent)
    {
        int t = tid >> 1, u = tid & 1;
        #pragma unroll
        for (int i = 0; i < 4; i++) {
            int un = u + 2*i;
            cp16(sb + (uint32_t)(QH_OFF + t*QP + un*4)*4, qh + qbase + (size_t)t*32 + un*4);
            cp16(sb + (uint32_t)(QL_OFF + t*QP + un*4)*4, ql + qbase + (size_t)t*32 + un*4);
        }
    }
    auto load_kv = [&](int kt, int s) {
        int kt0 = kt * TK;
        {
            int d2 = tid >> 3, j = tid & 7;
            #pragma unroll
            for (int i = 0; i < 4; i++) {
                int un = j + 8*i;
                cp16(sb + (uint32_t)(KH_OFF + s*4224 + d2*KB + un*4)*4, kh + kbase + (size_t)d2*T_ + kt0 + un*4);
                cp16(sb + (uint32_t)(KL_OFF + s*4224 + d2*KB + un*4)*4, kl + kbase + (size_t)d2*T_ + kt0 + un*4);
            }
        }
        {
            int t2 = tid >> 2, u = tid & 3;
            #pragma unroll
            for (int i = 0; i < 4; i++) {
                int un = u + 4*i;
                cp16(sb + (uint32_t)(VH_OFF + s*4352 + t2*VB + un*4)*4, vh + vbase + (size_t)(kt0/2 + t2)*64 + un*4);
                cp16(sb + (uint32_t)(VL_OFF + s*4352 + t2*VB + un*4)*4, vl + vbase + (size_t)(kt0/2 + t2)*64 + un*4);
            }
        }
    };

    load_kv(0, 0);
    CP_COMMIT();
    CP_WAIT0();
    __syncthreads();

    const int wq = wid * 16;
    const int qi0 = qt0 + wq + r, qi1 = qi0 + 8;
    float m0 = -1e30f, m1 = -1e30f, l0 = 0.f, l1 = 0.f;
    float oacc[8][4];
    #pragma unroll
    for (int i = 0; i < 8; i++)
        #pragma unroll
        for (int q = 0; q < 4; q++) oacc[i][q] = 0.f;

    const int NKT = T_ / TK;
    for (int kt = 0; kt < NKT; kt++) {
        const int s = kt & 1;
        if (kt + 1 < NKT) load_kv(kt + 1, (kt + 1) & 1);
        CP_COMMIT();

        const uint32_t* QsH = sm + QH_OFF;
        const uint32_t* QsL = sm + QL_OFF;
        const uint32_t* KsH = sm + KH_OFF + s*4224;
        const uint32_t* KsL = sm + KL_OFF + s*4224;
        const uint32_t* VsH = sm + VH_OFF + s*4352;
        const uint32_t* VsL = sm + VL_OFF + s*4352;

        // ---- scores ----
        float sacc[16][4];
        #pragma unroll
        for (int nt = 0; nt < 16; nt++)
            #pragma unroll
            for (int q = 0; q < 4; q++) sacc[nt][q] = 0.f;

        #pragma unroll
        for (int ks = 0; ks < 4; ks++) {
            const int k2 = ks * 8 + cq;
            uint32_t a_h[4], a_l[4];
            a_h[0] = QsH[(wq+r)*QP + k2];   a_h[1] = QsH[(wq+8+r)*QP + k2];
            a_h[2] = QsH[(wq+r)*QP + k2+4]; a_h[3] = QsH[(wq+8+r)*QP + k2+4];
            a_l[0] = QsL[(wq+r)*QP + k2];   a_l[1] = QsL[(wq+8+r)*QP + k2];
            a_l[2] = QsL[(wq+r)*QP + k2+4]; a_l[3] = QsL[(wq+8+r)*QP + k2+4];
            #pragma unroll
            for (int nt = 0; nt < 16; nt++) {
                uint32_t b_h[2], b_l[2];
                b_h[0] = KsH[k2*KB + nt*8 + r];
                b_h[1] = KsH[(k2+4)*KB + nt*8 + r];
                b_l[0] = KsL[k2*KB + nt*8 + r];
                b_l[1] = KsL[(k2+4)*KB + nt*8 + r];
                mma_bf16(sacc[nt], a_h, b_l);
                mma_bf16(sacc[nt], a_l, b_h);
                mma_bf16(sacc[nt], a_h, b_h);
            }
        }

        // ---- bias + online softmax ----
        float tm0 = -1e30f, tm1 = -1e30f;
        #pragma unroll
        for (int nt = 0; nt < 16; nt++) {
            int kj = kt*TK + nt*8 + 2*cq;
            int i00 = min(max(kj   - qi0, -MREL), MREL) + MREL;
            int i01 = min(max(kj+1 - qi0, -MREL), MREL) + MREL;
            int i10 = min(max(kj   - qi1, -MREL), MREL) + MREL;
            int i11 = min(max(kj+1 - qi1, -MREL), MREL) + MREL;
            sacc[nt][0] += rb_s[i00];
            sacc[nt][1] += rb_s[i01];
            sacc[nt][2] += rb_s[i10];
            sacc[nt][3] += rb_s[i11];
            tm0 = fmaxf(tm0, fmaxf(sacc[nt][0], sacc[nt][1]));
            tm1 = fmaxf(tm1, fmaxf(sacc[nt][2], sacc[nt][3]));
        }
        tm0 = qmax(tm0); tm1 = qmax(tm1);
        float nm0 = fmaxf(m0, tm0), nm1 = fmaxf(m1, tm1);
        float sc0 = __expf(m0 - nm0), sc1 = __expf(m1 - nm1);
        l0 *= sc0; l1 *= sc1;
        #pragma unroll
        for (int i = 0; i < 8; i++) {
            oacc[i][0] *= sc0; oacc[i][1] *= sc0;
            oacc[i][2] *= sc1; oacc[i][3] *= sc1;
        }
        float rs0 = 0.f, rs1 = 0.f;
        #pragma unroll
        for (int nt = 0; nt < 16; nt++) {
            float p0 = __expf(sacc[nt][0] - nm0);
            float p1 = __expf(sacc[nt][1] - nm0);
            float p2 = __expf(sacc[nt][2] - nm1);
            float p3 = __expf(sacc[nt][3] - nm1);
            sacc[nt][0] = p0; sacc[nt][1] = p1; sacc[nt][2] = p2; sacc[nt][3] = p3;
            rs0 += p0 + p1; rs1 += p2 + p3;
        }
        l0 += qsum(rs0); l1 += qsum(rs1);
        m0 = nm0; m1 = nm1;

        // ---- P @ V ----
        #pragma unroll
        for (int kk = 0; kk < 8; kk++) {
            uint32_t p_h[4], p_l[4];
            float ra, rb;
            p_h[0] = pack_hi(sacc[2*kk][0],   sacc[2*kk][1],   ra, rb); p_l[0] = pack_lo(ra, rb);
            p_h[1] = pack_hi(sacc[2*kk][2],   sacc[2*kk][3],   ra, rb); p_l[1] = pack_lo(ra, rb);
            p_h[2] = pack_hi(sacc[2*kk+1][0], sacc[2*kk+1][1], ra, rb); p_l[2] = pack_lo(ra, rb);
            p_h[3] = pack_hi(sacc[2*kk+1][2], sacc[2*kk+1][3], ra, rb); p_l[3] = pack_lo(ra, rb);
            const int t2 = kk * 8 + cq;
            #pragma unroll
            for (int ntd = 0; ntd < 8; ntd++) {
                uint32_t b_h[2], b_l[2];
                b_h[0] = VsH[t2*VB + ntd*8 + r];
                b_h[1] = VsH[(t2+4)*VB + ntd*8 + r];
                b_l[0] = VsL[t2*VB + ntd*8 + r];
                b_l[1] = VsL[(t2+4)*VB + ntd*8 + r];
                mma_bf16(oacc[ntd], p_h, b_l);
                mma_bf16(oacc[ntd], p_l, b_h);
                mma_bf16(oacc[ntd], p_h, b_h);
            }
        }

        CP_WAIT0();
        __syncthreads();
    }

    // ---- finalize + packed store (feeds proj GEMM) ----
    float inv0 = 1.f / l0, inv1 = 1.f / l1;
    const size_t ob0 = ((size_t)(b*T_ + qt0 + wq + r))*512 + h*32;
    const size_t ob1 = ((size_t)(b*T_ + qt0 + wq + r + 8))*512 + h*32;
    #pragma unroll
    for (int ntd = 0; ntd < 8; ntd++) {
        int d2 = ntd*4 + cq;
        float ra, rb;
        uint32_t w0 = pack_hi(oacc[ntd][0]*inv0, oacc[ntd][1]*inv0, ra, rb);
        uint32_t w0l = pack_lo(ra, rb);
        uint32_t w1 = pack_hi(oacc[ntd][2]*inv1, oacc[ntd][3]*inv1, ra, rb);
        uint32_t w1l = pack_lo(ra, rb);
        oh[ob0 + d2] = w0; ol[ob0 + d2] = w0l;
        oh[ob1 + d2] = w1; ol[ob1 + d2] = w1l;
    }
}

// ---------------- block reduction ----------------
__device__ __forceinline__ float block_reduce_sum(float v) {
    __shared__ float sh[33];
    int lane = threadIdx.x & 31, wid = threadIdx.x >> 5;
    #pragma unroll
    for (int o = 16; o > 0; o >>= 1) v += __shfl_xor_sync(0xffffffffu, v, o);
    if (lane == 0) sh[wid] = v;
    __syncthreads();
    if (wid == 0) {
        float t = (lane < 8) ? sh[lane] : 0.f;
        #pragma unroll
        for (int o = 4; o > 0; o >>= 1) t += __shfl_xor_sync(0xffffffffu, t, o);
        if (lane == 0) sh[32] = t;
    }
    __syncthreads();
    return sh[32];
}

// ---------------- LayerNorm fp32 out (for ln_in only) ----------------
__global__ void __launch_bounds__(256) ln_kernel(
    const float* __restrict__ x, const float* __restrict__ g,
    const float* __restrict__ b, float* __restrict__ y)
{
    int row = blockIdx.x;
    const float* xr = x + (size_t)row * D_;
    float v[4];
    float s = 0.f;
    #pragma unroll
    for (int j = 0; j < 4; j++) { v[j] = xr[threadIdx.x + j * 256]; s += v[j]; }
    float mean = block_reduce_sum(s) * (1.0f / D_);
    float var = 0.f;
    #pragma unroll
    for (int j = 0; j < 4; j++) { float d0 = v[j] - mean; var += d0 * d0; }
    var = block_reduce_sum(var) * (1.0f / D_);
    float rstd = rsqrtf(var + 1e-5f);
    float* yr = y + (size_t)row * D_;
    #pragma unroll
    for (int j = 0; j < 4; j++) {
        int c = threadIdx.x + j * 256;
        yr[c] = (v[j] - mean) * rstd * g[c] + b[c];
    }
}

// ---------------- LayerNorm -> packed hi/lo (feeds GEMMs) ----------------
__global__ void __launch_bounds__(256) ln_pack_kernel(
    const float* __restrict__ x, const float* __restrict__ g,
    const float* __restrict__ b, uint32_t* __restrict__ ah, uint32_t* __restrict__ al)
{
    int row = blockIdx.x;
    const float* xr = x + (size_t)row * D_;
    float4 v = *(const float4*)(xr + threadIdx.x * 4);
    float s = v.x + v.y + v.z + v.w;
    float mean = block_reduce_sum(s) * (1.0f / D_);
    float dx = v.x - mean, dy = v.y - mean, dz = v.z - mean, dw = v.w - mean;
    float var = dx*dx + dy*dy + dz*dz + dw*dw;
    var = block_reduce_sum(var) * (1.0f / D_);
    float rstd = rsqrtf(var + 1e-5f);
    int c = threadIdx.x * 4;
    float4 gg = *(const float4*)(g + c);
    float4 bb = *(const float4*)(b + c);
    float y0 = dx * rstd * gg.x + bb.x;
    float y1 = dy * rstd * gg.y + bb.y;
    float y2 = dz * rstd * gg.z + bb.z;
    float y3 = dw * rstd * gg.w + bb.w;
    float ra, rb;
    size_t base = (size_t)row * 512 + threadIdx.x * 2;
    ah[base]   = pack_hi(y0, y1, ra, rb); al[base]   = pack_lo(ra, rb);
    ah[base+1] = pack_hi(y2, y3, ra, rb); al[base+1] = pack_lo(ra, rb);
}

// ---------------- GeGLU -> packed hi/lo ----------------
__global__ void __launch_bounds__(256) geglu_pack_kernel(
    const float* __restrict__ ff1, uint32_t* __restrict__ ah, uint32_t* __restrict__ al)
{
    int idx = blockIdx.x * 256 + threadIdx.x;   // BT * 2048
    int m = idx >> 11, f2 = idx & 2047;
    float2 a = *(const float2*)(ff1 + (size_t)m * (2*FF_) + 2*f2);
    float2 g = *(const float2*)(ff1 + (size_t)m * (2*FF_) + FF_ + 2*f2);
    float ge0 = 0.5f * g.x * (1.0f + erff(g.x * 0.70710678118654752f));
    float ge1 = 0.5f * g.y * (1.0f + erff(g.y * 0.70710678118654752f));
    float v0 = a.x * ge0, v1 = a.y * ge1;
    float ra, rb;
    ah[idx] = pack_hi(v0, v1, ra, rb);
    al[idx] = pack_lo(ra, rb);
}

// ---------------- final scaling epilogue ----------------
__global__ void __launch_bounds__(256) final_kernel(
    const float* __restrict__ o, const float* __restrict__ alpha,
    const float* __restrict__ beta, const float* __restrict__ alpha_scale,
    const float* __restrict__ beta_scale, float* __restrict__ out)
{
    int row = blockIdx.x;
    const float* orow = o + (size_t)row * D_;
    float v[4];
    float ss = 0.f;
    #pragma unroll
    for (int j = 0; j < 4; j++) { v[j] = orow[threadIdx.x + j * 256]; ss += v[j] * v[j]; }
    ss = block_reduce_sum(ss);
    float ms = sqrtf(ss);
    float a_s = fminf(fmaxf(alpha_scale[0], 0.f), 1.f);
    float sc = 1.0f + alpha[0] * a_s * fminf(ms, 5.0f);
    float bb = beta[0] * beta_scale[0];
    #pragma unroll
    for (int j = 0; j < 4; j++) {
        int c = threadIdx.x + j * 256;
        float val = v[j] * sc + bb;
        val = fminf(fmaxf(val, -10.0f), 10.0f);
        out[(size_t)row * D_ + c] = val + v[j];
    }
}

// ---------------- launch ----------------
extern "C" void kernel_launch(void* const* d_in, const int* in_sizes, int n_in,
                              void* d_out, int out_size)
{
    const float* x           = (const float*)d_in[0];
    const float* context     = (const float*)d_in[1];
    const float* W_in        = (const float*)d_in[2];
    const float* b_in        = (const float*)d_in[3];
    const float* ln_in_g     = (const float*)d_in[4];
    const float* ln_in_b     = (const float*)d_in[5];
    const float* ln1_g       = (const float*)d_in[6];
    const float* ln1_b       = (const float*)d_in[7];
    const float* Wqkv        = (const float*)d_in[8];
    const float* bqkv        = (const float*)d_in[9];
    const float* Wproj       = (const float*)d_in[10];
    const float* bproj       = (const float*)d_in[11];
    const float* rel_bias    = (const float*)d_in[12];
    const float* ln2_g       = (const float*)d_in[13];
    const float* ln2_b       = (const float*)d_in[14];
    const float* Wfc1        = (const float*)d_in[15];
    const float* bfc1        = (const float*)d_in[16];
    const float* Wfc2        = (const float*)d_in[17];
    const float* bfc2        = (const float*)d_in[18];
    const float* ln_f_g      = (const float*)d_in[19];
    const float* ln_f_b      = (const float*)d_in[20];
    const float* W_out       = (const float*)d_in[21];
    const float* b_out       = (const float*)d_in[22];
    const float* alpha       = (const float*)d_in[23];
    const float* beta        = (const float*)d_in[24];
    const float* alpha_scale = (const float*)d_in[25];
    const float* beta_scale  = (const float*)d_in[26];
    float* out = (float*)d_out;

    float *h, *tmp, *qkv, *ff1;
    uint32_t *ah, *al, *wh, *wl, *qh, *ql, *kh, *kl, *vh, *vl;
    cudaGetSymbolAddress((void**)&h,   g_h);
    cudaGetSymbolAddress((void**)&tmp, g_tmp);
    cudaGetSymbolAddress((void**)&qkv, g_qkv);
    cudaGetSymbolAddress((void**)&ff1, g_ff1);
    cudaGetSymbolAddress((void**)&ah,  g_ah);
    cudaGetSymbolAddress((void**)&al,  g_al);
    cudaGetSymbolAddress((void**)&wh,  g_wh);
    cudaGetSymbolAddress((void**)&wl,  g_wl);
    cudaGetSymbolAddress((void**)&qh,  g_qh);
    cudaGetSymbolAddress((void**)&ql,  g_ql);
    cudaGetSymbolAddress((void**)&kh,  g_kh);
    cudaGetSymbolAddress((void**)&kl,  g_kl);
    cudaGetSymbolAddress((void**)&vh,  g_vh);
    cudaGetSymbolAddress((void**)&vl,  g_vl);

    cudaFuncSetAttribute(gemm_bf16x3<true,256>,  cudaFuncAttributeMaxDynamicSharedMemorySize, smb(256));
    cudaFuncSetAttribute(gemm_bf16x3<false,256>, cudaFuncAttributeMaxDynamicSharedMemorySize, smb(256));
    cudaFuncSetAttribute(gemm_bf16x3<true,128>,  cudaFuncAttributeMaxDynamicSharedMemorySize, smb(128));
    cudaFuncSetAttribute(gemm_bf16x3<false,128>, cudaFuncAttributeMaxDynamicSharedMemorySize, smb(128));
    cudaFuncSetAttribute(attn_kernel, cudaFuncAttributeMaxDynamicSharedMemorySize, ATT_SMEM_BYTES);

    // ---- weight pre-conversion ----
    convw_kernel<<<dim3((int)(WSZ_IN/256), 1),   256>>>(W_in,  wh + WOFF_IN,   wl + WOFF_IN,   D_,  D_);
    convw_kernel<<<dim3((int)(WSZ_QKV/256), L_), 256>>>(Wqkv,  wh + WOFF_QKV,  wl + WOFF_QKV,  D_,  3*D_);
    convw_kernel<<<dim3((int)(WSZ_PROJ/256), L_),256>>>(Wproj, wh + WOFF_PROJ, wl + WOFF_PROJ, D_,  D_);
    convw_kernel<<<dim3((int)(WSZ_FC1/256), L_), 256>>>(Wfc1,  wh + WOFF_FC1,  wl + WOFF_FC1,  D_,  2*FF_);
    convw_kernel<<<dim3((int)(WSZ_FC2/256), L_), 256>>>(Wfc2,  wh + WOFF_FC2,  wl + WOFF_FC2,  FF_, D_);
    convw_kernel<<<dim3((int)(WSZ_IN/256), 1),   256>>>(W_out, wh + WOFF_OUT,  wl + WOFF_OUT,  D_,  D_);

    // BN=256 for wide GEMMs (qkv, fc1); BN=128 for N=1024 GEMMs (fills 128/148 SMs)
    #define GEMM_W(RES, N, K, WOFF, bias, res, dst) \
        gemm_bf16x3<RES,256><<<dim3((N)/256, BT_/BM), 256, smb(256)>>>( \
            ah, al, wh + (WOFF), wl + (WOFF), (bias), (res), (dst), BT_, (N), (K))
    #define GEMM_N(RES, N, K, WOFF, bias, res, dst) \
        gemm_bf16x3<RES,128><<<dim3((N)/128, BT_/BM), 256, smb(128)>>>( \
            ah, al, wh + (WOFF), wl + (WOFF), (bias), (res), (dst), BT_, (N), (K))

    // pre: h = LN(x @ W_in + b_in + context)
    conva_kernel<<<(BT_*D_/2)/256, 256>>>(x, ah, al, D_/2);
    GEMM_N(true, D_, D_, WOFF_IN, b_in, context, tmp);
    ln_kernel<<<BT_, 256>>>(tmp, ln_in_g, ln_in_b, h);

    for (int l = 0; l < L_; l++) {
        // attention block
        ln_pack_kernel<<<BT_, 256>>>(h, ln1_g + l*D_, ln1_b + l*D_, ah, al);
        GEMM_W(false, 3*D_, D_, WOFF_QKV + (size_t)l*WSZ_QKV, bqkv + l*3*D_, nullptr, qkv);
        ropeconv_kernel<<<(B_*H_*T_*32)/256, 256>>>(qkv, qh, ql, kh, kl, vh, vl);
        attn_kernel<<<dim3(T_/TQ, B_*H_), 256, ATT_SMEM_BYTES>>>(
            qh, ql, kh, kl, vh, vl, rel_bias + (size_t)l*(2*MREL+1)*H_, ah, al);
        GEMM_N(true, D_, D_, WOFF_PROJ + (size_t)l*WSZ_PROJ, bproj + l*D_, h, h);

        // FFN block
        ln_pack_kernel<<<BT_, 256>>>(h, ln2_g + l*D_, ln2_b + l*D_, ah, al);
        GEMM_W(false, 2*FF_, D_, WOFF_FC1 + (size_t)l*WSZ_FC1, bfc1 + l*2*FF_, nullptr, ff1);
        geglu_pack_kernel<<<(BT_*FF_/2)/256, 256>>>(ff1, ah, al);
        GEMM_N(true, D_, FF_, WOFF_FC2 + (size_t)l*WSZ_FC2, bfc2 + l*D_, h, h);
    }

    // post
    ln_pack_kernel<<<BT_, 256>>>(h, ln_f_g, ln_f_b, ah, al);
    GEMM_N(false, D_, D_, WOFF_OUT, b_out, nullptr, tmp);
    final_kernel<<<BT_, 256>>>(tmp, alpha, beta, alpha_scale, beta_scale, out);
}